// round 3
// baseline (speedup 1.0000x reference)
#include <cuda_runtime.h>
#include <math.h>

#define L    2048
#define D    768
#define KF   24
#define KD   (KF * D)        /* 18432 */
#define JT   32              /* FIR truncation of the y-recurrence */
#define DD   (D * D)

#define BM 128
#define BN 64
#define BK 16

/* ---------------- scratch (device globals; no allocation allowed) ---------------- */
__device__ float g_vpT[KF * L];            /* filters * eig^(1/4), [k][t] layout   */
__device__ float g_xt[L * KD];             /* x_tilde [l][k*D+d], 151 MB           */
__device__ float g_delta[L * D];           /* delta_phi + delta_ar_u               */
__device__ float g_G[(JT + 1) * DD];       /* G_j = Phi_j^T bank                   */
__device__ float g_m1t[DD];                /* M1^T */
__device__ float g_m2t[DD];                /* M2^T */
__device__ float g_muT[3 * DD];            /* m_u transposed per lag: [k][i][o]    */
__device__ float g_RT[DD];                 /* doubling temp */

/* ---------------- small prep kernels ---------------- */
__global__ void prep_vp(const float* __restrict__ evals, const float* __restrict__ evecs) {
    int idx = blockIdx.x * blockDim.x + threadIdx.x;
    if (idx >= L * KF) return;
    int t = idx / KF, k = idx - t * KF;
    g_vpT[k * L + t] = evecs[idx] * powf(evals[k], 0.25f);
}

__global__ void prep_mats(const float* __restrict__ m_y, const float* __restrict__ m_u) {
    int idx = blockIdx.x * blockDim.x + threadIdx.x;
    if (idx >= DD) return;
    int i = idx / D, o = idx - i * D;           /* write [i][o] */
    float m1 = m_y[(o * 2 + 0) * D + i];
    float m2 = m_y[(o * 2 + 1) * D + i];
    g_m1t[idx] = m1;
    g_m2t[idx] = m2;
#pragma unroll
    for (int k = 0; k < 3; k++)
        g_muT[k * DD + idx] = m_u[((size_t)o * D + i) * 3 + k];
    g_G[idx] = (i == o) ? 1.f : 0.f;            /* G_0 = I      */
    g_G[DD + idx] = m1;                         /* G_1 = M1^T   */
}

/* ---------------- block-Toeplitz causal conv (shift-by-2 folded in) ----------------
   xt[l, k*D+d] = sum_t vp[t,k] * u[l-2-t, d]                                       */
__global__ void conv_kernel(const float* __restrict__ u) {
    const int k  = blockIdx.z;
    const int i  = blockIdx.y;               /* output 64-row block */
    const int d0 = blockIdx.x * 64;
    const int tid = threadIdx.x;
    const int tr = (tid >> 4) << 2;          /* 0..60 */
    const int tc = (tid & 15) << 2;          /* 0..60 */

    __shared__ float vseg[128];
    __shared__ float Us[64][64];

    float acc[4][4] = {};
    const float* vk = g_vpT + k * L;

    for (int j = 0; j <= i; j++) {
        int m = (i - j) * 64;
        if (tid < 128) {
            int t = m - 65 + tid;            /* t <= 2046 < L always */
            vseg[tid] = (t >= 0) ? vk[t] : 0.f;
        }
#pragma unroll
        for (int q = 0; q < 4; q++) {
            int idx4 = tid + q * 256;
            int rr = idx4 >> 4;
            int cc = (idx4 & 15) << 2;
            *(float4*)&Us[rr][cc] = *(const float4*)&u[(size_t)(j * 64 + rr) * D + d0 + cc];
        }
        __syncthreads();
#pragma unroll 4
        for (int s = 0; s < 64; s++) {
            /* A[r][s] = vp[m + r - s - 2] = vseg[r - s + 63] */
            float a0 = vseg[tr - s + 63];
            float a1 = vseg[tr - s + 64];
            float a2 = vseg[tr - s + 65];
            float a3 = vseg[tr - s + 66];
            float4 b = *(float4*)&Us[s][tc];
            acc[0][0] += a0 * b.x; acc[0][1] += a0 * b.y; acc[0][2] += a0 * b.z; acc[0][3] += a0 * b.w;
            acc[1][0] += a1 * b.x; acc[1][1] += a1 * b.y; acc[1][2] += a1 * b.z; acc[1][3] += a1 * b.w;
            acc[2][0] += a2 * b.x; acc[2][1] += a2 * b.y; acc[2][2] += a2 * b.z; acc[2][3] += a2 * b.w;
            acc[3][0] += a3 * b.x; acc[3][1] += a3 * b.y; acc[3][2] += a3 * b.z; acc[3][3] += a3 * b.w;
        }
        __syncthreads();
    }
#pragma unroll
    for (int rr = 0; rr < 4; rr++) {
        size_t off = (size_t)(i * 64 + tr + rr) * KD + (size_t)k * D + d0 + tc;
        *(float4*)&g_xt[off] = make_float4(acc[rr][0], acc[rr][1], acc[rr][2], acc[rr][3]);
    }
}

/* ---------------- generic tiled SGEMM: C[M,N] (+)= A @ B[K,N] ----------------
   MS=true: A is a [*, D] matrix read with a per-K-slab row shift j = q/D
            (element (l,q) -> A[(l - q/D)*lda + q%D], zero when row < 0).
   Batched via blockIdx.z with element offsets aB/bB/cB.                        */
template <bool MS>
__global__ void gemm_k(const float* __restrict__ A, const float* __restrict__ B,
                       float* __restrict__ C, int M, int N, int K, int lda,
                       int beta, int aB, int bB, int cB) {
    A += (size_t)blockIdx.z * aB;
    B += (size_t)blockIdx.z * bB;
    C += (size_t)blockIdx.z * cB;

    __shared__ float As[BK][BM];
    __shared__ float Bs[BK][BN];
    const int tid  = threadIdx.x;
    const int row0 = blockIdx.y * BM;
    const int col0 = blockIdx.x * BN;
    const int tr = (tid >> 4) << 3;          /* 0..120 */
    const int tc = (tid & 15) << 2;          /* 0..60  */
    float acc[8][4] = {};

    for (int k0 = 0; k0 < K; k0 += BK) {
#pragma unroll
        for (int q = 0; q < 2; q++) {        /* A tile: 128x16 = 512 float4 */
            int idx4 = tid + q * 256;
            int r  = idx4 >> 2;
            int kq = (idx4 & 3) << 2;
            float4 av;
            if (MS) {
                int qq = k0 + kq;            /* float4 never crosses a D boundary (D%4==0) */
                int j  = qq / D;
                int col = qq - j * D;
                int gr = row0 + r - j;
                av = (gr >= 0) ? *(const float4*)&A[(size_t)gr * lda + col]
                               : make_float4(0.f, 0.f, 0.f, 0.f);
            } else {
                av = *(const float4*)&A[(size_t)(row0 + r) * lda + k0 + kq];
            }
            As[kq + 0][r] = av.x;
            As[kq + 1][r] = av.y;
            As[kq + 2][r] = av.z;
            As[kq + 3][r] = av.w;
        }
        {                                    /* B tile: 16x64 = 256 float4 */
            int r  = tid >> 4;
            int c4 = (tid & 15) << 2;
            *(float4*)&Bs[r][c4] = *(const float4*)&B[(size_t)(k0 + r) * N + col0 + c4];
        }
        __syncthreads();
#pragma unroll
        for (int kk = 0; kk < BK; kk++) {
            float4 a0 = *(float4*)&As[kk][tr];
            float4 a1 = *(float4*)&As[kk][tr + 4];
            float4 bv = *(float4*)&Bs[kk][tc];
            float a[8] = {a0.x, a0.y, a0.z, a0.w, a1.x, a1.y, a1.z, a1.w};
            float b[4] = {bv.x, bv.y, bv.z, bv.w};
#pragma unroll
            for (int r = 0; r < 8; r++)
#pragma unroll
                for (int c = 0; c < 4; c++)
                    acc[r][c] += a[r] * b[c];
        }
        __syncthreads();
    }
#pragma unroll
    for (int r = 0; r < 8; r++) {
        size_t off = (size_t)(row0 + tr + r) * N + col0 + tc;
        float4 v = make_float4(acc[r][0], acc[r][1], acc[r][2], acc[r][3]);
        if (beta) {
            float4 c = *(float4*)&C[off];
            v.x += c.x; v.y += c.y; v.z += c.z; v.w += c.w;
        }
        *(float4*)&C[off] = v;
    }
}

/* ---------------- launch ---------------- */
extern "C" void kernel_launch(void* const* d_in, const int* in_sizes, int n_in,
                              void* d_out, int out_size) {
    const float* u      = (const float*)d_in[0];   /* [2048, 768]      */
    const float* m_y    = (const float*)d_in[1];   /* [768, 2, 768]    */
    const float* m_u    = (const float*)d_in[2];   /* [768, 768, 3]    */
    const float* m_phi  = (const float*)d_in[3];   /* [18432, 768]     */
    const float* evals  = (const float*)d_in[4];   /* [24]             */
    const float* evecs  = (const float*)d_in[5];   /* [2048, 24]       */
    float* y = (float*)d_out;                      /* [2048, 768]      */

    float *pxt, *pdl, *pG, *pm2t, *pmu, *pRT;
    cudaGetSymbolAddress((void**)&pxt,  g_xt);
    cudaGetSymbolAddress((void**)&pdl,  g_delta);
    cudaGetSymbolAddress((void**)&pG,   g_G);
    cudaGetSymbolAddress((void**)&pm2t, g_m2t);
    cudaGetSymbolAddress((void**)&pmu,  g_muT);
    cudaGetSymbolAddress((void**)&pRT,  g_RT);

    /* filters and transposed weight banks */
    prep_vp  <<<(L * KF + 255) / 256, 256>>>(evals, evecs);
    prep_mats<<<(DD + 255) / 256, 256>>>(m_y, m_u);

    /* spectral causal conv -> x_tilde (shift-by-2 folded in) */
    conv_kernel<<<dim3(D / 64, L / 64, KF), 256>>>(u);

    /* delta = x_tilde @ m_phi */
    gemm_k<false><<<dim3(D / BN, L / BM), 256>>>(pxt, m_phi, pdl, L, D, KD, KD, 0, 0, 0, 0);
    /* delta += AR-u: K = 3*D with per-lag row shift */
    gemm_k<true ><<<dim3(D / BN, L / BM), 256>>>(u, pmu, pdl, L, D, 3 * D, D, 1, 0, 0, 0);

    /* build G_j = Phi_j^T for j=2..32 via log-doubling.
       Companion-matrix identity: Phi_{m+i} = Phi_i Phi_m + Phi_{i-1} (M2 Phi_{m-1})
       => transposed: G_{m+i} = G_m @ G_i + RT @ G_{i-1},  RT = G_{m-1} @ M2^T.
       (A operand is the FIXED matrix; B is batched over i = 1..m.)              */
    const int mv[5] = {1, 2, 4, 8, 16};
    for (int s = 0; s < 5; s++) {
        int m = mv[s];
        gemm_k<false><<<dim3(D / BN, D / BM), 256>>>(pG + (size_t)(m - 1) * DD, pm2t, pRT,
                                                     D, D, D, D, 0, 0, 0, 0);
        /* G_{m+i} = G_m @ G_i   (A fixed = G_m, B batched = G_1..G_m) */
        gemm_k<false><<<dim3(D / BN, D / BM, m), 256>>>(pG + (size_t)m * DD, pG + DD,
                                                        pG + (size_t)(m + 1) * DD,
                                                        D, D, D, D, 0, 0, DD, DD);
        /* G_{m+i} += RT @ G_{i-1} (A fixed = RT, B batched = G_0..G_{m-1}) */
        gemm_k<false><<<dim3(D / BN, D / BM, m), 256>>>(pRT, pG,
                                                        pG + (size_t)(m + 1) * DD,
                                                        D, D, D, D, 1, 0, DD, DD);
    }

    /* y = sum_{j=0}^{32} shift_j(delta) @ G_j : single multishift GEMM, K = 33*D */
    gemm_k<true><<<dim3(D / BN, L / BM), 256>>>(pdl, pG, y, L, D, (JT + 1) * D, D, 0, 0, 0, 0);
}

// round 5
// speedup vs baseline: 3.0162x; 3.0162x over previous
#include <cuda_runtime.h>
#include <math.h>
#include <cstdint>

#define L    2048
#define D    768
#define KF   24
#define KD   (KF * D)        /* 18432 */
#define JT   32              /* FIR truncation of the y-recurrence */
#define DD   (D * D)

#define NS   3               /* cp.async pipeline stages */
#define TPB  256

/* SMEM layout per stage (floats): A 128 rows x 20 (16 used, pad->80B rows) = 2560,
   B 16 rows x 136 (128 used, pad) = 2176. Stage stride = 4736 floats = 18944 B. */
#define A_STRIDE_F 20
#define B_STRIDE_F 136
#define STAGE_F    4736
#define SMEM_SZ    (NS * STAGE_F * 4)

/* ---------------- scratch (device globals; no allocation allowed) ---------------- */
__device__ float g_vpT[KF * L];            /* filters * eig^(1/4), [k][t], tf32    */
__device__ float g_uR[L * D];              /* tf32-rounded inputs                  */
__device__ float g_phiR[(size_t)KD * D];   /* tf32-rounded m_phi                   */
__device__ float g_xt[(size_t)L * KD];     /* x_tilde [l][k*D+d]                   */
__device__ float g_delta[L * D];           /* delta_phi + delta_ar_u               */
__device__ float g_G[(JT + 1) * DD];       /* G_j = Phi_j^T bank (contiguous)      */
__device__ float g_m2t[DD];                /* M2^T (tf32)                          */
__device__ float g_muT[3 * DD];            /* m_u per lag [k][i][o] (tf32)         */
__device__ float g_AB[D * 2 * D];          /* [RT | G_m] concat for doubling       */

/* ---------------- helpers ---------------- */
__device__ __forceinline__ uint32_t s2u(const void* p) {
    uint32_t a;
    asm("{ .reg .u64 t; cvta.to.shared.u64 t, %1; cvt.u32.u64 %0, t; }" : "=r"(a) : "l"(p));
    return a;
}
__device__ __forceinline__ float tf32r(float x) {      /* round-to-nearest tf32 */
    float r; asm("cvt.rna.tf32.f32 %0, %1;" : "=f"(r) : "f"(x)); return r;
}

/* ---------------- small prep kernels ---------------- */
__global__ void prep_vp(const float* __restrict__ evals, const float* __restrict__ evecs) {
    int idx = blockIdx.x * blockDim.x + threadIdx.x;
    if (idx >= L * KF) return;
    int t = idx / KF, k = idx - t * KF;
    g_vpT[k * L + t] = tf32r(evecs[idx] * powf(evals[k], 0.25f));
}

__global__ void round_arr(const float* __restrict__ s, float* __restrict__ d, int n) {
    int i = blockIdx.x * blockDim.x + threadIdx.x;
    if (i < n) d[i] = tf32r(s[i]);
}

__global__ void prep_mats(const float* __restrict__ m_y, const float* __restrict__ m_u) {
    int idx = blockIdx.x * blockDim.x + threadIdx.x;
    if (idx >= DD) return;
    int i = idx / D, o = idx - i * D;                    /* write [i][o] */
    g_m2t[idx] = tf32r(m_y[(o * 2 + 1) * D + i]);        /* M2^T */
#pragma unroll
    for (int k = 0; k < 3; k++)
        g_muT[k * DD + idx] = tf32r(m_u[((size_t)o * D + i) * 3 + k]);
    g_G[idx] = (i == o) ? 1.f : 0.f;                     /* G_0 = I    */
    g_G[DD + idx] = tf32r(m_y[(o * 2 + 0) * D + i]);     /* G_1 = M1^T */
}

__global__ void copy_gm(int m) {                         /* g_AB[:, 768:1536] = G_m */
    int idx = blockIdx.x * blockDim.x + threadIdx.x;
    if (idx >= DD) return;
    int r = idx / D, c = idx - r * D;
    g_AB[r * (2 * D) + D + c] = g_G[(size_t)m * DD + idx];
}

/* ---------------- mma.sync tf32 GEMM: C[128x128 tile] (+)= op(A) @ B ----------------
   MODE 0 NORMAL : A[row, k]   = A[(row0+r)*lda + k0+k]
   MODE 1 MSHIFT : per-K-slab row shift j = k0/D (BK=16 tiles never straddle a slab)
   MODE 2 TOEP   : A[row, k]   = vp[row - k - 2] (0 if neg); triangular Kend.
   Batched over blockIdx.z with element strides aB/bB/cB. All operands pre-rounded tf32. */
template <int MODE>
__global__ void __launch_bounds__(TPB, 2)
tgemm(const float* __restrict__ A, const float* __restrict__ B, float* __restrict__ C,
      int K, int lda, int ldb, int ldc, int beta, int rnd, int aB, int bB, int cB) {
    extern __shared__ float sm[];
    A += (size_t)blockIdx.z * aB;
    B += (size_t)blockIdx.z * bB;
    C += (size_t)blockIdx.z * cB;

    const int row0 = blockIdx.y * 128, col0 = blockIdx.x * 128;
    const int tid = threadIdx.x, lane = tid & 31, wid = tid >> 5;
    const int wm = wid & 1, wn = wid >> 1;       /* warp tile: 64 rows x 32 cols */
    const int g = lane >> 2, tig = lane & 3;

    const int Kend = (MODE == 2) ? min(K, row0 + 128) : K;
    const int T = Kend >> 4;

    float c[4][4][4];
#pragma unroll
    for (int a = 0; a < 4; a++)
#pragma unroll
        for (int b = 0; b < 4; b++)
#pragma unroll
            for (int e = 0; e < 4; e++) c[a][b][e] = 0.f;

    auto load_stage = [&](int st, int k0) {
        float* As = sm + st * STAGE_F;
        float* Bs = As + 2560;
        uint32_t abase = s2u(As), bbase = s2u(Bs);
        /* A tile: 128 rows x 16 k = 512 16B chunks */
#pragma unroll
        for (int q = 0; q < 2; q++) {
            int id = tid + q * 256;
            int r = id >> 2, c4 = id & 3;
            uint32_t dst = abase + r * 80 + c4 * 16;
            if (MODE == 2) {
                int kk = k0 + c4 * 4;
                int t0 = row0 + r - 2 - kk;
                float4 v;
                v.x = (t0 >= 0) ? A[t0]     : 0.f;
                v.y = (t0 >= 1) ? A[t0 - 1] : 0.f;
                v.z = (t0 >= 2) ? A[t0 - 2] : 0.f;
                v.w = (t0 >= 3) ? A[t0 - 3] : 0.f;
                *(float4*)((char*)As + r * 80 + c4 * 16) = v;
            } else if (MODE == 1) {
                int j = k0 / D, colb = k0 - j * D;
                int gr = row0 + r - j;
                const float* src = A + (size_t)max(gr, 0) * lda + colb + c4 * 4;
                uint32_t sz = (gr >= 0) ? 16u : 0u;
                asm volatile("cp.async.cg.shared.global [%0], [%1], 16, %2;"
                             :: "r"(dst), "l"(src), "r"(sz) : "memory");
            } else {
                const float* src = A + (size_t)(row0 + r) * lda + k0 + c4 * 4;
                asm volatile("cp.async.cg.shared.global [%0], [%1], 16;"
                             :: "r"(dst), "l"(src) : "memory");
            }
        }
        /* B tile: 16 k-rows x 128 n = 512 chunks */
#pragma unroll
        for (int q = 0; q < 2; q++) {
            int id = tid + q * 256;
            int kr = id >> 5, c4 = id & 31;
            uint32_t dst = bbase + kr * (B_STRIDE_F * 4) + c4 * 16;
            const float* src = B + (size_t)(k0 + kr) * ldb + col0 + c4 * 4;
            asm volatile("cp.async.cg.shared.global [%0], [%1], 16;"
                         :: "r"(dst), "l"(src) : "memory");
        }
    };

    /* prologue: stages 0..NS-2 */
#pragma unroll
    for (int s = 0; s < NS - 1; s++) {
        if (s < T) load_stage(s, s * 16);
        asm volatile("cp.async.commit_group;" ::: "memory");
    }

    for (int t = 0; t < T; t++) {
        asm volatile("cp.async.wait_group %0;" :: "n"(NS - 2) : "memory");
        __syncthreads();
        if (t + NS - 1 < T) load_stage((t + NS - 1) % NS, (t + NS - 1) * 16);
        asm volatile("cp.async.commit_group;" ::: "memory");

        float* As = sm + (t % NS) * STAGE_F;
        const uint32_t* Bsu = (const uint32_t*)(As + 2560);
        uint32_t abase = s2u(As);
#pragma unroll
        for (int kst = 0; kst < 2; kst++) {
            uint32_t af[4][4];
#pragma unroll
            for (int mt = 0; mt < 4; mt++) {
                uint32_t addr = abase + (wm * 64 + mt * 16 + (lane & 15)) * 80
                              + kst * 32 + ((lane >> 4) << 4);
                asm volatile("ldmatrix.sync.aligned.m8n8.x4.shared.b16 {%0,%1,%2,%3}, [%4];"
                    : "=r"(af[mt][0]), "=r"(af[mt][1]), "=r"(af[mt][2]), "=r"(af[mt][3])
                    : "r"(addr));
            }
            uint32_t bf[4][2];
#pragma unroll
            for (int nt = 0; nt < 4; nt++) {
                int nn = wn * 32 + nt * 8 + g;
                bf[nt][0] = Bsu[(kst * 8 + tig) * B_STRIDE_F + nn];
                bf[nt][1] = Bsu[(kst * 8 + tig + 4) * B_STRIDE_F + nn];
            }
#pragma unroll
            for (int mt = 0; mt < 4; mt++)
#pragma unroll
                for (int nt = 0; nt < 4; nt++)
                    asm volatile("mma.sync.aligned.m16n8k8.row.col.f32.tf32.tf32.f32 "
                        "{%0,%1,%2,%3},{%4,%5,%6,%7},{%8,%9},{%0,%1,%2,%3};"
                        : "+f"(c[mt][nt][0]), "+f"(c[mt][nt][1]),
                          "+f"(c[mt][nt][2]), "+f"(c[mt][nt][3])
                        : "r"(af[mt][0]), "r"(af[mt][1]), "r"(af[mt][2]), "r"(af[mt][3]),
                          "r"(bf[nt][0]), "r"(bf[nt][1]));
        }
    }

    /* epilogue */
#pragma unroll
    for (int mt = 0; mt < 4; mt++)
#pragma unroll
        for (int nt = 0; nt < 4; nt++) {
            int rr = row0 + wm * 64 + mt * 16 + g;
            int cc = col0 + wn * 32 + nt * 8 + tig * 2;
            float2* p0 = (float2*)&C[(size_t)rr * ldc + cc];
            float2* p1 = (float2*)&C[(size_t)(rr + 8) * ldc + cc];
            float2 v0 = make_float2(c[mt][nt][0], c[mt][nt][1]);
            float2 v1 = make_float2(c[mt][nt][2], c[mt][nt][3]);
            if (beta) {
                float2 o0 = *p0, o1 = *p1;
                v0.x += o0.x; v0.y += o0.y; v1.x += o1.x; v1.y += o1.y;
            }
            if (rnd) {
                v0.x = tf32r(v0.x); v0.y = tf32r(v0.y);
                v1.x = tf32r(v1.x); v1.y = tf32r(v1.y);
            }
            *p0 = v0; *p1 = v1;
        }
}

/* ---------------- launch ---------------- */
extern "C" void kernel_launch(void* const* d_in, const int* in_sizes, int n_in,
                              void* d_out, int out_size) {
    const float* u      = (const float*)d_in[0];   /* [2048, 768]   */
    const float* m_y    = (const float*)d_in[1];   /* [768, 2, 768] */
    const float* m_u    = (const float*)d_in[2];   /* [768, 768, 3] */
    const float* m_phi  = (const float*)d_in[3];   /* [18432, 768]  */
    const float* evals  = (const float*)d_in[4];   /* [24]          */
    const float* evecs  = (const float*)d_in[5];   /* [2048, 24]    */
    float* y = (float*)d_out;                      /* [2048, 768]   */

    float *pvp, *puR, *pphiR, *pxt, *pdl, *pG, *pm2t, *pmu, *pab;
    cudaGetSymbolAddress((void**)&pvp,   g_vpT);
    cudaGetSymbolAddress((void**)&puR,   g_uR);
    cudaGetSymbolAddress((void**)&pphiR, g_phiR);
    cudaGetSymbolAddress((void**)&pxt,   g_xt);
    cudaGetSymbolAddress((void**)&pdl,   g_delta);
    cudaGetSymbolAddress((void**)&pG,    g_G);
    cudaGetSymbolAddress((void**)&pm2t,  g_m2t);
    cudaGetSymbolAddress((void**)&pmu,   g_muT);
    cudaGetSymbolAddress((void**)&pab,   g_AB);

    cudaFuncSetAttribute(tgemm<0>, cudaFuncAttributeMaxDynamicSharedMemorySize, SMEM_SZ);
    cudaFuncSetAttribute(tgemm<1>, cudaFuncAttributeMaxDynamicSharedMemorySize, SMEM_SZ);
    cudaFuncSetAttribute(tgemm<2>, cudaFuncAttributeMaxDynamicSharedMemorySize, SMEM_SZ);

    prep_vp  <<<(L * KF + 255) / 256, 256>>>(evals, evecs);
    prep_mats<<<(DD + 255) / 256, 256>>>(m_y, m_u);
    round_arr<<<(L * D + 255) / 256, 256>>>(u, puR, L * D);
    round_arr<<<(KD * D + 255) / 256, 256>>>(m_phi, pphiR, KD * D);

    /* conv: X_k = Toeplitz(vp_k) @ U (triangular), into x_tilde layout; round out */
    tgemm<2><<<dim3(D / 128, L / 128, KF), TPB, SMEM_SZ>>>(
        pvp, puR, pxt, L, 0, D, KD, 0, 1, L, 0, D);

    /* delta = x_tilde @ m_phi (keep f32, re-rounded after AR add) */
    tgemm<0><<<dim3(D / 128, L / 128), TPB, SMEM_SZ>>>(
        pxt, pphiR, pdl, KD, KD, D, D, 0, 0, 0, 0, 0);
    /* delta += AR-u (K = 3D, per-lag row shift); round out */
    tgemm<1><<<dim3(D / 128, L / 128), TPB, SMEM_SZ>>>(
        puR, pmu, pdl, 3 * D, D, D, D, 1, 1, 0, 0, 0);

    /* Phi^T bank by doubling: G_{m+i} = G_m G_i + (G_{m-1} M2^T) G_{i-1}
       = [RT | G_m] @ [G_{i-1}; G_i] (stacked B contiguous in bank) */
    const int mv[5] = {1, 2, 4, 8, 16};
    for (int s = 0; s < 5; s++) {
        int m = mv[s];
        tgemm<0><<<dim3(D / 128, D / 128), TPB, SMEM_SZ>>>(
            pG + (size_t)(m - 1) * DD, pm2t, pab, D, D, D, 2 * D, 0, 1, 0, 0, 0);
        copy_gm<<<(DD + 255) / 256, 256>>>(m);
        tgemm<0><<<dim3(D / 128, D / 128, m), TPB, SMEM_SZ>>>(
            pab, pG, pG + (size_t)(m + 1) * DD, 2 * D, 2 * D, D, D, 0, 1, 0, DD, DD);
    }

    /* y = sum_{j=0}^{32} shift_j(delta) @ G_j : single multishift GEMM, K = 33D */
    tgemm<1><<<dim3(D / 128, L / 128), TPB, SMEM_SZ>>>(
        pdl, pG, y, (JT + 1) * D, D, D, D, 0, 0, 0, 0, 0);
}

// round 6
// speedup vs baseline: 3.8750x; 1.2848x over previous
#include <cuda_runtime.h>
#include <math.h>
#include <cstdint>

#define L    2048
#define D    768
#define KF   24
#define KD   (KF * D)        /* 18432 */
#define JT   32              /* FIR truncation of the y-recurrence */
#define DD   (D * D)

#define NS   3               /* cp.async pipeline stages */
#define TPB  256

/* SMEM layout per stage (floats): A 128 rows x 20 (16 used, pad->80B rows) = 2560,
   B 16 rows x 136 (128 used, pad) = 2176. Stage stride = 4736 floats = 18944 B. */
#define A_STRIDE_F 20
#define B_STRIDE_F 136
#define STAGE_F    4736
#define SMEM_SZ    (NS * STAGE_F * 4)

/* ---------------- scratch (device globals; no allocation allowed) ---------------- */
__device__ float g_vpT[KF * L];            /* filters * eig^(1/4), [k][t], tf32    */
__device__ float g_uR[L * D];              /* tf32-rounded inputs                  */
__device__ float g_phiR[(size_t)KD * D];   /* tf32-rounded m_phi                   */
__device__ float g_xt[(size_t)L * KD];     /* x_tilde [l][k*D+d]                   */
__device__ float g_delta[L * D];           /* delta_phi + delta_ar_u               */
__device__ float g_G[(JT + 1) * DD];       /* G_j = Phi_j^T bank (contiguous)      */
__device__ float g_m2t[DD];                /* M2^T (tf32)                          */
__device__ float g_muT[3 * DD];            /* m_u per lag [k][i][o] (tf32)         */
__device__ float g_AB[D * 2 * D];          /* [RT | G_m] concat for doubling       */
__device__ float g_part[5 * L * D];        /* split-K partial outputs              */

/* ---------------- helpers ---------------- */
__device__ __forceinline__ uint32_t s2u(const void* p) {
    uint32_t a;
    asm("{ .reg .u64 t; cvta.to.shared.u64 t, %1; cvt.u32.u64 %0, t; }" : "=r"(a) : "l"(p));
    return a;
}
__device__ __forceinline__ float tf32r(float x) {      /* round-to-nearest tf32 */
    float r; asm("cvt.rna.tf32.f32 %0, %1;" : "=f"(r) : "f"(x)); return r;
}

/* ---------------- small prep kernels ---------------- */
__global__ void prep_vp(const float* __restrict__ evals, const float* __restrict__ evecs) {
    int idx = blockIdx.x * blockDim.x + threadIdx.x;
    if (idx >= L * KF) return;
    int t = idx / KF, k = idx - t * KF;
    g_vpT[k * L + t] = tf32r(evecs[idx] * powf(evals[k], 0.25f));
}

__global__ void round_arr(const float* __restrict__ s, float* __restrict__ d, int n) {
    int i = blockIdx.x * blockDim.x + threadIdx.x;
    if (i < n) d[i] = tf32r(s[i]);
}

__global__ void prep_mats(const float* __restrict__ m_y, const float* __restrict__ m_u) {
    int idx = blockIdx.x * blockDim.x + threadIdx.x;
    if (idx >= DD) return;
    int i = idx / D, o = idx - i * D;                    /* write [i][o] */
    g_m2t[idx] = tf32r(m_y[(o * 2 + 1) * D + i]);        /* M2^T */
#pragma unroll
    for (int k = 0; k < 3; k++)
        g_muT[k * DD + idx] = tf32r(m_u[((size_t)o * D + i) * 3 + k]);
    g_G[idx] = (i == o) ? 1.f : 0.f;                     /* G_0 = I    */
    g_G[DD + idx] = tf32r(m_y[(o * 2 + 0) * D + i]);     /* G_1 = M1^T */
}

__global__ void copy_gm(int m) {                         /* g_AB[:, 768:1536] = G_m */
    int idx = blockIdx.x * blockDim.x + threadIdx.x;
    if (idx >= DD) return;
    int r = idx / D, c = idx - r * D;
    g_AB[r * (2 * D) + D + c] = g_G[(size_t)m * DD + idx];
}

/* reduce np split-K partials (stride L*D) -> out; optional tf32 round. float4 wide. */
__global__ void reduce_p(const float* __restrict__ p, int np, float* __restrict__ out, int rnd) {
    int i = blockIdx.x * blockDim.x + threadIdx.x;
    if (i >= (L * D) / 4) return;
    float4 s = ((const float4*)p)[i];
    for (int z = 1; z < np; z++) {
        float4 v = ((const float4*)(p + (size_t)z * L * D))[i];
        s.x += v.x; s.y += v.y; s.z += v.z; s.w += v.w;
    }
    if (rnd) { s.x = tf32r(s.x); s.y = tf32r(s.y); s.z = tf32r(s.z); s.w = tf32r(s.w); }
    ((float4*)out)[i] = s;
}

/* ---------------- mma.sync tf32 GEMM: C[128x128 tile] (+)= op(A) @ B ----------------
   MODE 0 NORMAL : A[row, k]   = A[(row0+r)*lda + k0+k]
   MODE 1 MSHIFT : per-K-slab row shift j = jzs*z + k0/D (BK=16 never straddles a slab)
   MODE 2 TOEP   : A[row, k]   = vp[row - k - 2] (0 if neg); triangular Kend.
   Batched / split-K over blockIdx.z with element strides aB/bB/cB.                    */
template <int MODE>
__global__ void __launch_bounds__(TPB, 2)
tgemm(const float* __restrict__ A, const float* __restrict__ B, float* __restrict__ C,
      int K, int lda, int ldb, int ldc, int beta, int rnd, int jzs,
      int aB, int bB, int cB) {
    extern __shared__ float sm[];
    A += (size_t)blockIdx.z * aB;
    B += (size_t)blockIdx.z * bB;
    C += (size_t)blockIdx.z * cB;
    const int jbase = jzs * blockIdx.z;

    const int row0 = blockIdx.y * 128, col0 = blockIdx.x * 128;
    const int tid = threadIdx.x, lane = tid & 31, wid = tid >> 5;
    const int wm = wid & 1, wn = wid >> 1;       /* warp tile: 64 rows x 32 cols */
    const int g = lane >> 2, tig = lane & 3;

    const int Kend = (MODE == 2) ? min(K, row0 + 128) : K;
    const int T = Kend >> 4;

    float c[4][4][4];
#pragma unroll
    for (int a = 0; a < 4; a++)
#pragma unroll
        for (int b = 0; b < 4; b++)
#pragma unroll
            for (int e = 0; e < 4; e++) c[a][b][e] = 0.f;

    auto load_stage = [&](int st, int k0) {
        float* As = sm + st * STAGE_F;
        float* Bs = As + 2560;
        uint32_t abase = s2u(As), bbase = s2u(Bs);
        /* A tile: 128 rows x 16 k = 512 16B chunks */
#pragma unroll
        for (int q = 0; q < 2; q++) {
            int id = tid + q * 256;
            int r = id >> 2, c4 = id & 3;
            uint32_t dst = abase + r * 80 + c4 * 16;
            if (MODE == 2) {
                int kk = k0 + c4 * 4;
                int t0 = row0 + r - 2 - kk;
                float4 v;
                v.x = (t0 >= 0) ? A[t0]     : 0.f;
                v.y = (t0 >= 1) ? A[t0 - 1] : 0.f;
                v.z = (t0 >= 2) ? A[t0 - 2] : 0.f;
                v.w = (t0 >= 3) ? A[t0 - 3] : 0.f;
                *(float4*)((char*)As + r * 80 + c4 * 16) = v;
            } else if (MODE == 1) {
                int j = jbase + k0 / D, colb = k0 - (k0 / D) * D;
                int gr = row0 + r - j;
                const float* src = A + (size_t)max(gr, 0) * lda + colb + c4 * 4;
                uint32_t sz = (gr >= 0) ? 16u : 0u;
                asm volatile("cp.async.cg.shared.global [%0], [%1], 16, %2;"
                             :: "r"(dst), "l"(src), "r"(sz) : "memory");
            } else {
                const float* src = A + (size_t)(row0 + r) * lda + k0 + c4 * 4;
                asm volatile("cp.async.cg.shared.global [%0], [%1], 16;"
                             :: "r"(dst), "l"(src) : "memory");
            }
        }
        /* B tile: 16 k-rows x 128 n = 512 chunks */
#pragma unroll
        for (int q = 0; q < 2; q++) {
            int id = tid + q * 256;
            int kr = id >> 5, c4 = id & 31;
            uint32_t dst = bbase + kr * (B_STRIDE_F * 4) + c4 * 16;
            const float* src = B + (size_t)(k0 + kr) * ldb + col0 + c4 * 4;
            asm volatile("cp.async.cg.shared.global [%0], [%1], 16;"
                         :: "r"(dst), "l"(src) : "memory");
        }
    };

    /* prologue: stages 0..NS-2 */
#pragma unroll
    for (int s = 0; s < NS - 1; s++) {
        if (s < T) load_stage(s, s * 16);
        asm volatile("cp.async.commit_group;" ::: "memory");
    }

    for (int t = 0; t < T; t++) {
        asm volatile("cp.async.wait_group %0;" :: "n"(NS - 2) : "memory");
        __syncthreads();
        if (t + NS - 1 < T) load_stage((t + NS - 1) % NS, (t + NS - 1) * 16);
        asm volatile("cp.async.commit_group;" ::: "memory");

        float* As = sm + (t % NS) * STAGE_F;
        const uint32_t* Bsu = (const uint32_t*)(As + 2560);
        uint32_t abase = s2u(As);
#pragma unroll
        for (int kst = 0; kst < 2; kst++) {
            uint32_t af[4][4];
#pragma unroll
            for (int mt = 0; mt < 4; mt++) {
                uint32_t addr = abase + (wm * 64 + mt * 16 + (lane & 15)) * 80
                              + kst * 32 + ((lane >> 4) << 4);
                asm volatile("ldmatrix.sync.aligned.m8n8.x4.shared.b16 {%0,%1,%2,%3}, [%4];"
                    : "=r"(af[mt][0]), "=r"(af[mt][1]), "=r"(af[mt][2]), "=r"(af[mt][3])
                    : "r"(addr));
            }
            uint32_t bf[4][2];
#pragma unroll
            for (int nt = 0; nt < 4; nt++) {
                int nn = wn * 32 + nt * 8 + g;
                bf[nt][0] = Bsu[(kst * 8 + tig) * B_STRIDE_F + nn];
                bf[nt][1] = Bsu[(kst * 8 + tig + 4) * B_STRIDE_F + nn];
            }
#pragma unroll
            for (int mt = 0; mt < 4; mt++)
#pragma unroll
                for (int nt = 0; nt < 4; nt++)
                    asm volatile("mma.sync.aligned.m16n8k8.row.col.f32.tf32.tf32.f32 "
                        "{%0,%1,%2,%3},{%4,%5,%6,%7},{%8,%9},{%0,%1,%2,%3};"
                        : "+f"(c[mt][nt][0]), "+f"(c[mt][nt][1]),
                          "+f"(c[mt][nt][2]), "+f"(c[mt][nt][3])
                        : "r"(af[mt][0]), "r"(af[mt][1]), "r"(af[mt][2]), "r"(af[mt][3]),
                          "r"(bf[nt][0]), "r"(bf[nt][1]));
        }
    }

    /* epilogue */
#pragma unroll
    for (int mt = 0; mt < 4; mt++)
#pragma unroll
        for (int nt = 0; nt < 4; nt++) {
            int rr = row0 + wm * 64 + mt * 16 + g;
            int cc = col0 + wn * 32 + nt * 8 + tig * 2;
            float2* p0 = (float2*)&C[(size_t)rr * ldc + cc];
            float2* p1 = (float2*)&C[(size_t)(rr + 8) * ldc + cc];
            float2 v0 = make_float2(c[mt][nt][0], c[mt][nt][1]);
            float2 v1 = make_float2(c[mt][nt][2], c[mt][nt][3]);
            if (beta) {
                float2 o0 = *p0, o1 = *p1;
                v0.x += o0.x; v0.y += o0.y; v1.x += o1.x; v1.y += o1.y;
            }
            if (rnd) {
                v0.x = tf32r(v0.x); v0.y = tf32r(v0.y);
                v1.x = tf32r(v1.x); v1.y = tf32r(v1.y);
            }
            *p0 = v0; *p1 = v1;
        }
}

/* ---------------- launch ---------------- */
extern "C" void kernel_launch(void* const* d_in, const int* in_sizes, int n_in,
                              void* d_out, int out_size) {
    const float* u      = (const float*)d_in[0];   /* [2048, 768]   */
    const float* m_y    = (const float*)d_in[1];   /* [768, 2, 768] */
    const float* m_u    = (const float*)d_in[2];   /* [768, 768, 3] */
    const float* m_phi  = (const float*)d_in[3];   /* [18432, 768]  */
    const float* evals  = (const float*)d_in[4];   /* [24]          */
    const float* evecs  = (const float*)d_in[5];   /* [2048, 24]    */
    float* y = (float*)d_out;                      /* [2048, 768]   */

    float *pvp, *puR, *pphiR, *pxt, *pdl, *pG, *pm2t, *pmu, *pab, *pP;
    cudaGetSymbolAddress((void**)&pvp,   g_vpT);
    cudaGetSymbolAddress((void**)&puR,   g_uR);
    cudaGetSymbolAddress((void**)&pphiR, g_phiR);
    cudaGetSymbolAddress((void**)&pxt,   g_xt);
    cudaGetSymbolAddress((void**)&pdl,   g_delta);
    cudaGetSymbolAddress((void**)&pG,    g_G);
    cudaGetSymbolAddress((void**)&pm2t,  g_m2t);
    cudaGetSymbolAddress((void**)&pmu,   g_muT);
    cudaGetSymbolAddress((void**)&pab,   g_AB);
    cudaGetSymbolAddress((void**)&pP,    g_part);

    cudaFuncSetAttribute(tgemm<0>, cudaFuncAttributeMaxDynamicSharedMemorySize, SMEM_SZ);
    cudaFuncSetAttribute(tgemm<1>, cudaFuncAttributeMaxDynamicSharedMemorySize, SMEM_SZ);
    cudaFuncSetAttribute(tgemm<2>, cudaFuncAttributeMaxDynamicSharedMemorySize, SMEM_SZ);

    prep_vp  <<<(L * KF + 255) / 256, 256>>>(evals, evecs);
    prep_mats<<<(DD + 255) / 256, 256>>>(m_y, m_u);
    round_arr<<<(L * D + 255) / 256, 256>>>(u, puR, L * D);
    round_arr<<<(KD * D + 255) / 256, 256>>>(m_phi, pphiR, KD * D);

    /* conv: X_k = Toeplitz(vp_k) @ U (triangular), into x_tilde layout; round out */
    tgemm<2><<<dim3(D / 128, L / 128, KF), TPB, SMEM_SZ>>>(
        pvp, puR, pxt, L, 0, D, KD, 0, 1, 0, L, 0, D);

    /* delta_phi = x_tilde @ m_phi, split-K x4 (K=4608 each) -> partials 0..3 */
    tgemm<0><<<dim3(D / 128, L / 128, 4), TPB, SMEM_SZ>>>(
        pxt, pphiR, pP, KD / 4, KD, D, D, 0, 0, 0, KD / 4, (KD / 4) * D, L * D);
    /* delta_ar_u -> partial 4 (K = 3D, per-lag row shift) */
    tgemm<1><<<dim3(D / 128, L / 128), TPB, SMEM_SZ>>>(
        puR, pmu, pP + (size_t)4 * L * D, 3 * D, D, D, D, 0, 0, 0, 0, 0, 0);
    /* delta = sum of 5 partials, tf32-rounded */
    reduce_p<<<(L * D / 4 + 255) / 256, 256>>>(pP, 5, pdl, 1);

    /* Phi^T bank by doubling: G_{m+i} = G_m G_i + (G_{m-1} M2^T) G_{i-1}
       = [RT | G_m] @ [G_{i-1}; G_i] (stacked B contiguous in bank) */
    const int mv[5] = {1, 2, 4, 8, 16};
    for (int s = 0; s < 5; s++) {
        int m = mv[s];
        tgemm<0><<<dim3(D / 128, D / 128), TPB, SMEM_SZ>>>(
            pG + (size_t)(m - 1) * DD, pm2t, pab, D, D, D, 2 * D, 0, 1, 0, 0, 0, 0);
        copy_gm<<<(DD + 255) / 256, 256>>>(m);
        tgemm<0><<<dim3(D / 128, D / 128, m), TPB, SMEM_SZ>>>(
            pab, pG, pG + (size_t)(m + 1) * DD, 2 * D, 2 * D, D, D, 0, 1, 0, 0, DD, DD);
    }

    /* y = sum_j shift_j(delta) @ G_j : multishift GEMM, 33 slabs split x3 (11 each) */
    tgemm<1><<<dim3(D / 128, L / 128, 3), TPB, SMEM_SZ>>>(
        pdl, pG, pP, 11 * D, D, D, D, 0, 0, 11, 0, 11 * DD, L * D);
    reduce_p<<<(L * D / 4 + 255) / 256, 256>>>(pP, 3, y, 0);
}

// round 7
// speedup vs baseline: 4.2772x; 1.1038x over previous
#include <cuda_runtime.h>
#include <math.h>
#include <cstdint>

#define L    2048
#define D    768
#define KF   24
#define KD   (KF * D)        /* 18432 */
#define JT   32              /* FIR truncation of the y-recurrence */
#define DD   (D * D)

#define NS   3               /* cp.async pipeline stages */
#define TPB  256

/* SMEM per stage (floats): A 128x20 (80B rows) = 2560, B 16x136 = 2176 -> 4736 */
#define B_STRIDE_F 136
#define STAGE_F    4736
#define SMEM_SZ    (NS * STAGE_F * 4)

/* ---------------- scratch (device globals; no allocation allowed) ---------------- */
__device__ float g_vpT[KF * L];            /* filters * eig^(1/4), [k][t], tf32    */
__device__ float g_uR[L * D];              /* tf32-rounded inputs                  */
__device__ float g_phiR[(size_t)KD * D];   /* tf32-rounded m_phi                   */
__device__ float g_xt[(size_t)L * KD];     /* x_tilde [l][k*D+d]                   */
__device__ float g_delta[L * D];           /* delta_phi + delta_ar_u               */
__device__ float g_G[(JT + 1) * DD];       /* G_j = Phi_j^T bank (contiguous)      */
__device__ float g_m2t[DD];                /* M2^T (tf32)                          */
__device__ float g_muT[3 * DD];            /* m_u per lag [k][i][o] (tf32)         */
__device__ float g_AB[D * 2 * D];          /* [RT | G_m] concat for doubling       */
__device__ float g_part[5 * L * D];        /* split-K partial outputs              */

/* ---------------- helpers ---------------- */
__device__ __forceinline__ uint32_t s2u(const void* p) {
    uint32_t a;
    asm("{ .reg .u64 t; cvta.to.shared.u64 t, %1; cvt.u32.u64 %0, t; }" : "=r"(a) : "l"(p));
    return a;
}
__device__ __forceinline__ float tf32r(float x) {      /* round-to-nearest tf32 */
    float r; asm("cvt.rna.tf32.f32 %0, %1;" : "=f"(r) : "f"(x)); return r;
}

/* ---------------- small prep kernels ---------------- */
__global__ void prep_vp(const float* __restrict__ evals, const float* __restrict__ evecs) {
    int idx = blockIdx.x * blockDim.x + threadIdx.x;
    if (idx >= L * KF) return;
    int t = idx / KF, k = idx - t * KF;
    g_vpT[k * L + t] = tf32r(evecs[idx] * powf(evals[k], 0.25f));
}

__global__ void round_arr(const float* __restrict__ s, float* __restrict__ d, int n) {
    int i = blockIdx.x * blockDim.x + threadIdx.x;
    if (i < n) d[i] = tf32r(s[i]);
}

__global__ void prep_mats(const float* __restrict__ m_y, const float* __restrict__ m_u) {
    int idx = blockIdx.x * blockDim.x + threadIdx.x;
    if (idx >= DD) return;
    int i = idx / D, o = idx - i * D;                    /* write [i][o] */
    g_m2t[idx] = tf32r(m_y[(o * 2 + 1) * D + i]);        /* M2^T */
#pragma unroll
    for (int k = 0; k < 3; k++)
        g_muT[k * DD + idx] = tf32r(m_u[((size_t)o * D + i) * 3 + k]);
    g_G[idx] = (i == o) ? 1.f : 0.f;                     /* G_0 = I    */
    g_G[DD + idx] = tf32r(m_y[(o * 2 + 0) * D + i]);     /* G_1 = M1^T */
}

__global__ void copy_gm(int m) {                         /* g_AB[:, 768:1536] = G_m */
    int idx = blockIdx.x * blockDim.x + threadIdx.x;
    if (idx >= DD) return;
    int r = idx / D, c = idx - r * D;
    g_AB[r * (2 * D) + D + c] = g_G[(size_t)m * DD + idx];
}

/* reduce np split-K partials (stride L*D) -> out; optional tf32 round. float4 wide. */
__global__ void reduce_p(const float* __restrict__ p, int np, float* __restrict__ out, int rnd) {
    int i = blockIdx.x * blockDim.x + threadIdx.x;
    if (i >= (L * D) / 4) return;
    float4 s = ((const float4*)p)[i];
    for (int z = 1; z < np; z++) {
        float4 v = ((const float4*)(p + (size_t)z * L * D))[i];
        s.x += v.x; s.y += v.y; s.z += v.z; s.w += v.w;
    }
    if (rnd) { s.x = tf32r(s.x); s.y = tf32r(s.y); s.z = tf32r(s.z); s.w = tf32r(s.w); }
    ((float4*)out)[i] = s;
}

/* ---------------- mma.sync tf32 GEMM: C[128x128 tile] (+)= op(A) @ B ----------------
   MODE 0 NORMAL : A[row, k]   = A[(row0+r)*lda + k0+k]
   MODE 1 MSHIFT : per-K-slab row shift j = jzs*z + k0/D (BK=16 never straddles a slab)
   MODE 2 TOEP   : A[row, k]   = vp[row - k - 2] (0 if neg); triangular Kend.
   Batched / split-K over blockIdx.z with element strides aB/bB/cB.                    */
template <int MODE>
__global__ void __launch_bounds__(TPB, 2)
tgemm(const float* __restrict__ A, const float* __restrict__ B, float* __restrict__ C,
      int K, int lda, int ldb, int ldc, int beta, int rnd, int jzs,
      int aB, int bB, int cB) {
    extern __shared__ float sm[];
    A += (size_t)blockIdx.z * aB;
    B += (size_t)blockIdx.z * bB;
    C += (size_t)blockIdx.z * cB;
    const int jbase = jzs * blockIdx.z;

    const int row0 = blockIdx.y * 128, col0 = blockIdx.x * 128;
    const int tid = threadIdx.x, lane = tid & 31, wid = tid >> 5;
    const int wm = wid & 1, wn = wid >> 1;       /* warp tile: 64 rows x 32 cols */
    const int g = lane >> 2, tig = lane & 3;

    const int Kend = (MODE == 2) ? min(K, row0 + 128) : K;
    const int T = Kend >> 4;

    float c[4][4][4];
#pragma unroll
    for (int a = 0; a < 4; a++)
#pragma unroll
        for (int b = 0; b < 4; b++)
#pragma unroll
            for (int e = 0; e < 4; e++) c[a][b][e] = 0.f;

    auto load_stage = [&](int st, int k0) {
        float* As = sm + st * STAGE_F;
        float* Bs = As + 2560;
        uint32_t abase = s2u(As), bbase = s2u(Bs);
        /* A tile: 128 rows x 16 k = 512 16B chunks */
#pragma unroll
        for (int q = 0; q < 2; q++) {
            int id = tid + q * 256;
            int r = id >> 2, c4 = id & 3;
            uint32_t dst = abase + r * 80 + c4 * 16;
            if (MODE == 2) {
                int kk = k0 + c4 * 4;
                int t0 = row0 + r - 2 - kk;
                float4 v;
                v.x = (t0 >= 0) ? A[t0]     : 0.f;
                v.y = (t0 >= 1) ? A[t0 - 1] : 0.f;
                v.z = (t0 >= 2) ? A[t0 - 2] : 0.f;
                v.w = (t0 >= 3) ? A[t0 - 3] : 0.f;
                *(float4*)((char*)As + r * 80 + c4 * 16) = v;
            } else if (MODE == 1) {
                int j = jbase + k0 / D, colb = k0 - (k0 / D) * D;
                int gr = row0 + r - j;
                const float* src = A + (size_t)max(gr, 0) * lda + colb + c4 * 4;
                uint32_t sz = (gr >= 0) ? 16u : 0u;
                asm volatile("cp.async.cg.shared.global [%0], [%1], 16, %2;"
                             :: "r"(dst), "l"(src), "r"(sz) : "memory");
            } else {
                const float* src = A + (size_t)(row0 + r) * lda + k0 + c4 * 4;
                asm volatile("cp.async.cg.shared.global [%0], [%1], 16;"
                             :: "r"(dst), "l"(src) : "memory");
            }
        }
        /* B tile: 16 k-rows x 128 n = 512 chunks */
#pragma unroll
        for (int q = 0; q < 2; q++) {
            int id = tid + q * 256;
            int kr = id >> 5, c4 = id & 31;
            uint32_t dst = bbase + kr * (B_STRIDE_F * 4) + c4 * 16;
            const float* src = B + (size_t)(k0 + kr) * ldb + col0 + c4 * 4;
            asm volatile("cp.async.cg.shared.global [%0], [%1], 16;"
                         :: "r"(dst), "l"(src) : "memory");
        }
    };

    /* prologue: stages 0..NS-2 */
#pragma unroll
    for (int s = 0; s < NS - 1; s++) {
        if (s < T) load_stage(s, s * 16);
        asm volatile("cp.async.commit_group;" ::: "memory");
    }

    for (int t = 0; t < T; t++) {
        asm volatile("cp.async.wait_group %0;" :: "n"(NS - 2) : "memory");
        __syncthreads();
        if (t + NS - 1 < T) load_stage((t + NS - 1) % NS, (t + NS - 1) * 16);
        asm volatile("cp.async.commit_group;" ::: "memory");

        float* As = sm + (t % NS) * STAGE_F;
        const uint32_t* Bsu = (const uint32_t*)(As + 2560);
        uint32_t abase = s2u(As);
#pragma unroll
        for (int kst = 0; kst < 2; kst++) {
            uint32_t af[4][4];
#pragma unroll
            for (int mt = 0; mt < 4; mt++) {
                uint32_t addr = abase + (wm * 64 + mt * 16 + (lane & 15)) * 80
                              + kst * 32 + ((lane >> 4) << 4);
                asm volatile("ldmatrix.sync.aligned.m8n8.x4.shared.b16 {%0,%1,%2,%3}, [%4];"
                    : "=r"(af[mt][0]), "=r"(af[mt][1]), "=r"(af[mt][2]), "=r"(af[mt][3])
                    : "r"(addr));
            }
            uint32_t bf[4][2];
#pragma unroll
            for (int nt = 0; nt < 4; nt++) {
                int nn = wn * 32 + nt * 8 + g;
                bf[nt][0] = Bsu[(kst * 8 + tig) * B_STRIDE_F + nn];
                bf[nt][1] = Bsu[(kst * 8 + tig + 4) * B_STRIDE_F + nn];
            }
#pragma unroll
            for (int mt = 0; mt < 4; mt++)
#pragma unroll
                for (int nt = 0; nt < 4; nt++)
                    asm volatile("mma.sync.aligned.m16n8k8.row.col.f32.tf32.tf32.f32 "
                        "{%0,%1,%2,%3},{%4,%5,%6,%7},{%8,%9},{%0,%1,%2,%3};"
                        : "+f"(c[mt][nt][0]), "+f"(c[mt][nt][1]),
                          "+f"(c[mt][nt][2]), "+f"(c[mt][nt][3])
                        : "r"(af[mt][0]), "r"(af[mt][1]), "r"(af[mt][2]), "r"(af[mt][3]),
                          "r"(bf[nt][0]), "r"(bf[nt][1]));
        }
    }

    /* epilogue */
#pragma unroll
    for (int mt = 0; mt < 4; mt++)
#pragma unroll
        for (int nt = 0; nt < 4; nt++) {
            int rr = row0 + wm * 64 + mt * 16 + g;
            int cc = col0 + wn * 32 + nt * 8 + tig * 2;
            float2* p0 = (float2*)&C[(size_t)rr * ldc + cc];
            float2* p1 = (float2*)&C[(size_t)(rr + 8) * ldc + cc];
            float2 v0 = make_float2(c[mt][nt][0], c[mt][nt][1]);
            float2 v1 = make_float2(c[mt][nt][2], c[mt][nt][3]);
            if (beta) {
                float2 o0 = *p0, o1 = *p1;
                v0.x += o0.x; v0.y += o0.y; v1.x += o1.x; v1.y += o1.y;
            }
            if (rnd) {
                v0.x = tf32r(v0.x); v0.y = tf32r(v0.y);
                v1.x = tf32r(v1.x); v1.y = tf32r(v1.y);
            }
            *p0 = v0; *p1 = v1;
        }
}

/* ---------------- launch ---------------- */
extern "C" void kernel_launch(void* const* d_in, const int* in_sizes, int n_in,
                              void* d_out, int out_size) {
    const float* u      = (const float*)d_in[0];   /* [2048, 768]   */
    const float* m_y    = (const float*)d_in[1];   /* [768, 2, 768] */
    const float* m_u    = (const float*)d_in[2];   /* [768, 768, 3] */
    const float* m_phi  = (const float*)d_in[3];   /* [18432, 768]  */
    const float* evals  = (const float*)d_in[4];   /* [24]          */
    const float* evecs  = (const float*)d_in[5];   /* [2048, 24]    */
    float* y = (float*)d_out;                      /* [2048, 768]   */

    float *pvp, *puR, *pphiR, *pxt, *pdl, *pG, *pm2t, *pmu, *pab, *pP;
    cudaGetSymbolAddress((void**)&pvp,   g_vpT);
    cudaGetSymbolAddress((void**)&puR,   g_uR);
    cudaGetSymbolAddress((void**)&pphiR, g_phiR);
    cudaGetSymbolAddress((void**)&pxt,   g_xt);
    cudaGetSymbolAddress((void**)&pdl,   g_delta);
    cudaGetSymbolAddress((void**)&pG,    g_G);
    cudaGetSymbolAddress((void**)&pm2t,  g_m2t);
    cudaGetSymbolAddress((void**)&pmu,   g_muT);
    cudaGetSymbolAddress((void**)&pab,   g_AB);
    cudaGetSymbolAddress((void**)&pP,    g_part);

    cudaFuncSetAttribute(tgemm<0>, cudaFuncAttributeMaxDynamicSharedMemorySize, SMEM_SZ);
    cudaFuncSetAttribute(tgemm<1>, cudaFuncAttributeMaxDynamicSharedMemorySize, SMEM_SZ);
    cudaFuncSetAttribute(tgemm<2>, cudaFuncAttributeMaxDynamicSharedMemorySize, SMEM_SZ);

    /* Side stream for the Phi-bank chain (depends only on m_y/m_u) + m_phi round.
       Created fresh per call (kernel_launch runs only for correctness + capture);
       not destroyed here since its captured nodes must survive until EndCapture. */
    cudaStream_t s1;
    cudaEvent_t evF, evP, evU, ev1;
    cudaStreamCreateWithFlags(&s1, cudaStreamNonBlocking);
    cudaEventCreateWithFlags(&evF, cudaEventDisableTiming);
    cudaEventCreateWithFlags(&evP, cudaEventDisableTiming);
    cudaEventCreateWithFlags(&evU, cudaEventDisableTiming);
    cudaEventCreateWithFlags(&ev1, cudaEventDisableTiming);

    /* fork: s1 joins the capture graph by waiting on an origin-stream event */
    cudaEventRecord(evF, 0);
    cudaStreamWaitEvent(s1, evF, 0);

    /* ---- stream 0: input-dependent chain ---- */
    prep_vp  <<<(L * KF + 255) / 256, 256>>>(evals, evecs);
    round_arr<<<(L * D + 255) / 256, 256>>>(u, puR, L * D);
    cudaEventRecord(evU, 0);

    /* conv: X_k = Toeplitz(vp_k) @ U (triangular), into x_tilde layout; round out */
    tgemm<2><<<dim3(D / 128, L / 128, KF), TPB, SMEM_SZ>>>(
        pvp, puR, pxt, L, 0, D, KD, 0, 1, 0, L, 0, D);

    /* ---- stream 1: weight-only chain, overlapped with conv ---- */
    round_arr<<<(KD * D + 255) / 256, 256, 0, s1>>>(m_phi, pphiR, KD * D);
    cudaEventRecord(evP, s1);
    prep_mats<<<(DD + 255) / 256, 256, 0, s1>>>(m_y, m_u);

    /* Phi^T bank by doubling: G_{m+i} = G_m G_i + (G_{m-1} M2^T) G_{i-1}
       = [RT | G_m] @ [G_{i-1}; G_i] (stacked B contiguous in bank) */
    const int mv[5] = {1, 2, 4, 8, 16};
    for (int s = 0; s < 5; s++) {
        int m = mv[s];
        tgemm<0><<<dim3(D / 128, D / 128), TPB, SMEM_SZ, s1>>>(
            pG + (size_t)(m - 1) * DD, pm2t, pab, D, D, D, 2 * D, 0, 1, 0, 0, 0, 0);
        copy_gm<<<(DD + 255) / 256, 256, 0, s1>>>(m);
        tgemm<0><<<dim3(D / 128, D / 128, m), TPB, SMEM_SZ, s1>>>(
            pab, pG, pG + (size_t)(m + 1) * DD, 2 * D, 2 * D, D, D, 0, 1, 0, 0, DD, DD);
    }
    /* delta_ar_u -> partial 3 (needs rounded u from stream 0) */
    cudaStreamWaitEvent(s1, evU, 0);
    tgemm<1><<<dim3(D / 128, L / 128), TPB, SMEM_SZ, s1>>>(
        puR, pmu, pP + (size_t)3 * L * D, 3 * D, D, D, D, 0, 0, 0, 0, 0, 0);
    cudaEventRecord(ev1, s1);

    /* ---- stream 0 continues: phi GEMM (needs rounded m_phi) ---- */
    cudaStreamWaitEvent(0, evP, 0);
    /* delta_phi = x_tilde @ m_phi, split-K x3 (K=6144 each, 288 CTAs = 1 wave) */
    tgemm<0><<<dim3(D / 128, L / 128, 3), TPB, SMEM_SZ>>>(
        pxt, pphiR, pP, KD / 3, KD, D, D, 0, 0, 0, KD / 3, (KD / 3) * D, L * D);

    /* join: AR partial + Phi bank ready */
    cudaStreamWaitEvent(0, ev1, 0);
    /* delta = sum of 4 partials, tf32-rounded */
    reduce_p<<<(L * D / 4 + 255) / 256, 256>>>(pP, 4, pdl, 1);

    /* y = sum_j shift_j(delta) @ G_j : multishift GEMM, 33 slabs split x3 (11 each) */
    tgemm<1><<<dim3(D / 128, L / 128, 3), TPB, SMEM_SZ>>>(
        pdl, pG, pP, 11 * D, D, D, D, 0, 0, 11, 0, 11 * DD, L * D);
    reduce_p<<<(L * D / 4 + 255) / 256, 256>>>(pP, 3, y, 0);
}

// round 8
// speedup vs baseline: 4.6000x; 1.0755x over previous
#include <cuda_runtime.h>
#include <math.h>
#include <cstdint>

#define L    2048
#define D    768
#define KF   24
#define KD   (KF * D)        /* 18432 */
#define JT   26              /* FIR truncation of the y-recurrence (27 taps, 3x9 split) */
#define DD   (D * D)

#define NS   4               /* cp.async pipeline stages */
#define TPB  256

/* SMEM per stage (floats): A 128x20 (80B rows) = 2560, B 16x136 = 2176 -> 4736 */
#define B_STRIDE_F 136
#define STAGE_F    4736
#define SMEM_SZ    (NS * STAGE_F * 4)

/* ---------------- scratch (device globals; no allocation allowed) ---------------- */
__device__ float g_vpT[KF * L];            /* filters * eig^(1/4), [k][t], tf32    */
__device__ float g_uR[L * D];              /* tf32-rounded inputs                  */
__device__ float g_phiR[(size_t)KD * D];   /* tf32-rounded m_phi                   */
__device__ float g_xt[(size_t)L * KD];     /* x_tilde [l][k*D+d]                   */
__device__ float g_delta[L * D];           /* delta_phi + delta_ar_u               */
__device__ float g_G[(JT + 1) * DD];       /* G_j = Phi_j^T bank (contiguous)      */
__device__ float g_m2t[DD];                /* M2^T (tf32)                          */
__device__ float g_muT[3 * DD];            /* m_u per lag [k][i][o] (tf32)         */
__device__ float g_AB[D * 2 * D];          /* [RT | G_m] concat for doubling       */
__device__ float g_part[5 * L * D];        /* split-K partial outputs              */

/* ---------------- helpers ---------------- */
__device__ __forceinline__ uint32_t s2u(const void* p) {
    uint32_t a;
    asm("{ .reg .u64 t; cvta.to.shared.u64 t, %1; cvt.u32.u64 %0, t; }" : "=r"(a) : "l"(p));
    return a;
}
__device__ __forceinline__ float tf32r(float x) {      /* round-to-nearest tf32 */
    float r; asm("cvt.rna.tf32.f32 %0, %1;" : "=f"(r) : "f"(x)); return r;
}

/* ---------------- small prep kernels ---------------- */
__global__ void prep_vp(const float* __restrict__ evals, const float* __restrict__ evecs) {
    int idx = blockIdx.x * blockDim.x + threadIdx.x;
    if (idx >= L * KF) return;
    int t = idx / KF, k = idx - t * KF;
    g_vpT[k * L + t] = tf32r(evecs[idx] * powf(evals[k], 0.25f));
}

__global__ void round_arr(const float* __restrict__ s, float* __restrict__ d, int n) {
    int i = blockIdx.x * blockDim.x + threadIdx.x;
    if (i < n) d[i] = tf32r(s[i]);
}

__global__ void prep_mats(const float* __restrict__ m_y, const float* __restrict__ m_u) {
    int idx = blockIdx.x * blockDim.x + threadIdx.x;
    if (idx >= DD) return;
    int i = idx / D, o = idx - i * D;                    /* write [i][o] */
    g_m2t[idx] = tf32r(m_y[(o * 2 + 1) * D + i]);        /* M2^T */
#pragma unroll
    for (int k = 0; k < 3; k++)
        g_muT[k * DD + idx] = tf32r(m_u[((size_t)o * D + i) * 3 + k]);
    g_G[idx] = (i == o) ? 1.f : 0.f;                     /* G_0 = I    */
    g_G[DD + idx] = tf32r(m_y[(o * 2 + 0) * D + i]);     /* G_1 = M1^T */
}

__global__ void copy_gm(int m) {                         /* g_AB[:, 768:1536] = G_m */
    int idx = blockIdx.x * blockDim.x + threadIdx.x;
    if (idx >= DD) return;
    int r = idx / D, c = idx - r * D;
    g_AB[r * (2 * D) + D + c] = g_G[(size_t)m * DD + idx];
}

/* reduce np split-K partials (stride L*D) -> out; optional tf32 round. float4 wide. */
__global__ void reduce_p(const float* __restrict__ p, int np, float* __restrict__ out, int rnd) {
    int i = blockIdx.x * blockDim.x + threadIdx.x;
    if (i >= (L * D) / 4) return;
    float4 s = ((const float4*)p)[i];
    for (int z = 1; z < np; z++) {
        float4 v = ((const float4*)(p + (size_t)z * L * D))[i];
        s.x += v.x; s.y += v.y; s.z += v.z; s.w += v.w;
    }
    if (rnd) { s.x = tf32r(s.x); s.y = tf32r(s.y); s.z = tf32r(s.z); s.w = tf32r(s.w); }
    ((float4*)out)[i] = s;
}

/* ---------------- mma.sync tf32 GEMM: C[128x128 tile] (+)= op(A) @ B ----------------
   MODE 0 NORMAL : A[row, k]   = A[(row0+r)*lda + k0+k]
   MODE 1 MSHIFT : per-K-slab row shift j = jzs*z + k0/D (BK=16 never straddles a slab)
   MODE 2 TOEP   : A[row, k]   = vp[row - k - 2] (0 if neg); triangular Kend;
                   y-blocks reversed so heaviest CTAs launch first (work-steal balance).
   Batched / split-K over blockIdx.z with element strides aB/bB/cB.                    */
template <int MODE>
__global__ void __launch_bounds__(TPB, 2)
tgemm(const float* __restrict__ A, const float* __restrict__ B, float* __restrict__ C,
      int K, int lda, int ldb, int ldc, int beta, int rnd, int jzs,
      int aB, int bB, int cB) {
    extern __shared__ float sm[];
    A += (size_t)blockIdx.z * aB;
    B += (size_t)blockIdx.z * bB;
    C += (size_t)blockIdx.z * cB;
    const int jbase = jzs * blockIdx.z;

    const int yb = (MODE == 2) ? (gridDim.y - 1 - blockIdx.y) : blockIdx.y;
    const int row0 = yb * 128, col0 = blockIdx.x * 128;
    const int tid = threadIdx.x, lane = tid & 31, wid = tid >> 5;
    const int wm = wid & 1, wn = wid >> 1;       /* warp tile: 64 rows x 32 cols */
    const int g = lane >> 2, tig = lane & 3;

    const int Kend = (MODE == 2) ? min(K, row0 + 128) : K;
    const int T = Kend >> 4;

    float c[4][4][4];
#pragma unroll
    for (int a = 0; a < 4; a++)
#pragma unroll
        for (int b = 0; b < 4; b++)
#pragma unroll
            for (int e = 0; e < 4; e++) c[a][b][e] = 0.f;

    auto load_stage = [&](int st, int k0) {
        float* As = sm + st * STAGE_F;
        float* Bs = As + 2560;
        uint32_t abase = s2u(As), bbase = s2u(Bs);
        /* A tile: 128 rows x 16 k = 512 16B chunks */
#pragma unroll
        for (int q = 0; q < 2; q++) {
            int id = tid + q * 256;
            int r = id >> 2, c4 = id & 3;
            uint32_t dst = abase + r * 80 + c4 * 16;
            if (MODE == 2) {
                int kk = k0 + c4 * 4;
                int t0 = row0 + r - 2 - kk;
                float4 v;
                v.x = (t0 >= 0) ? A[t0]     : 0.f;
                v.y = (t0 >= 1) ? A[t0 - 1] : 0.f;
                v.z = (t0 >= 2) ? A[t0 - 2] : 0.f;
                v.w = (t0 >= 3) ? A[t0 - 3] : 0.f;
                *(float4*)((char*)As + r * 80 + c4 * 16) = v;
            } else if (MODE == 1) {
                int j = jbase + k0 / D, colb = k0 - (k0 / D) * D;
                int gr = row0 + r - j;
                const float* src = A + (size_t)max(gr, 0) * lda + colb + c4 * 4;
                uint32_t sz = (gr >= 0) ? 16u : 0u;
                asm volatile("cp.async.cg.shared.global [%0], [%1], 16, %2;"
                             :: "r"(dst), "l"(src), "r"(sz) : "memory");
            } else {
                const float* src = A + (size_t)(row0 + r) * lda + k0 + c4 * 4;
                asm volatile("cp.async.cg.shared.global [%0], [%1], 16;"
                             :: "r"(dst), "l"(src) : "memory");
            }
        }
        /* B tile: 16 k-rows x 128 n = 512 chunks */
#pragma unroll
        for (int q = 0; q < 2; q++) {
            int id = tid + q * 256;
            int kr = id >> 5, c4 = id & 31;
            uint32_t dst = bbase + kr * (B_STRIDE_F * 4) + c4 * 16;
            const float* src = B + (size_t)(k0 + kr) * ldb + col0 + c4 * 4;
            asm volatile("cp.async.cg.shared.global [%0], [%1], 16;"
                         :: "r"(dst), "l"(src) : "memory");
        }
    };

    /* prologue: stages 0..NS-2 */
#pragma unroll
    for (int s = 0; s < NS - 1; s++) {
        if (s < T) load_stage(s, s * 16);
        asm volatile("cp.async.commit_group;" ::: "memory");
    }

    for (int t = 0; t < T; t++) {
        asm volatile("cp.async.wait_group %0;" :: "n"(NS - 2) : "memory");
        __syncthreads();
        if (t + NS - 1 < T) load_stage((t + NS - 1) % NS, (t + NS - 1) * 16);
        asm volatile("cp.async.commit_group;" ::: "memory");

        float* As = sm + (t % NS) * STAGE_F;
        const uint32_t* Bsu = (const uint32_t*)(As + 2560);
        uint32_t abase = s2u(As);
#pragma unroll
        for (int kst = 0; kst < 2; kst++) {
            uint32_t af[4][4];
#pragma unroll
            for (int mt = 0; mt < 4; mt++) {
                uint32_t addr = abase + (wm * 64 + mt * 16 + (lane & 15)) * 80
                              + kst * 32 + ((lane >> 4) << 4);
                asm volatile("ldmatrix.sync.aligned.m8n8.x4.shared.b16 {%0,%1,%2,%3}, [%4];"
                    : "=r"(af[mt][0]), "=r"(af[mt][1]), "=r"(af[mt][2]), "=r"(af[mt][3])
                    : "r"(addr));
            }
            uint32_t bf[4][2];
#pragma unroll
            for (int nt = 0; nt < 4; nt++) {
                int nn = wn * 32 + nt * 8 + g;
                bf[nt][0] = Bsu[(kst * 8 + tig) * B_STRIDE_F + nn];
                bf[nt][1] = Bsu[(kst * 8 + tig + 4) * B_STRIDE_F + nn];
            }
#pragma unroll
            for (int mt = 0; mt < 4; mt++)
#pragma unroll
                for (int nt = 0; nt < 4; nt++)
                    asm volatile("mma.sync.aligned.m16n8k8.row.col.f32.tf32.tf32.f32 "
                        "{%0,%1,%2,%3},{%4,%5,%6,%7},{%8,%9},{%0,%1,%2,%3};"
                        : "+f"(c[mt][nt][0]), "+f"(c[mt][nt][1]),
                          "+f"(c[mt][nt][2]), "+f"(c[mt][nt][3])
                        : "r"(af[mt][0]), "r"(af[mt][1]), "r"(af[mt][2]), "r"(af[mt][3]),
                          "r"(bf[nt][0]), "r"(bf[nt][1]));
        }
    }

    /* epilogue */
#pragma unroll
    for (int mt = 0; mt < 4; mt++)
#pragma unroll
        for (int nt = 0; nt < 4; nt++) {
            int rr = row0 + wm * 64 + mt * 16 + g;
            int cc = col0 + wn * 32 + nt * 8 + tig * 2;
            float2* p0 = (float2*)&C[(size_t)rr * ldc + cc];
            float2* p1 = (float2*)&C[(size_t)(rr + 8) * ldc + cc];
            float2 v0 = make_float2(c[mt][nt][0], c[mt][nt][1]);
            float2 v1 = make_float2(c[mt][nt][2], c[mt][nt][3]);
            if (beta) {
                float2 o0 = *p0, o1 = *p1;
                v0.x += o0.x; v0.y += o0.y; v1.x += o1.x; v1.y += o1.y;
            }
            if (rnd) {
                v0.x = tf32r(v0.x); v0.y = tf32r(v0.y);
                v1.x = tf32r(v1.x); v1.y = tf32r(v1.y);
            }
            *p0 = v0; *p1 = v1;
        }
}

/* ---------------- launch ---------------- */
extern "C" void kernel_launch(void* const* d_in, const int* in_sizes, int n_in,
                              void* d_out, int out_size) {
    const float* u      = (const float*)d_in[0];   /* [2048, 768]   */
    const float* m_y    = (const float*)d_in[1];   /* [768, 2, 768] */
    const float* m_u    = (const float*)d_in[2];   /* [768, 768, 3] */
    const float* m_phi  = (const float*)d_in[3];   /* [18432, 768]  */
    const float* evals  = (const float*)d_in[4];   /* [24]          */
    const float* evecs  = (const float*)d_in[5];   /* [2048, 24]    */
    float* y = (float*)d_out;                      /* [2048, 768]   */

    float *pvp, *puR, *pphiR, *pxt, *pdl, *pG, *pm2t, *pmu, *pab, *pP;
    cudaGetSymbolAddress((void**)&pvp,   g_vpT);
    cudaGetSymbolAddress((void**)&puR,   g_uR);
    cudaGetSymbolAddress((void**)&pphiR, g_phiR);
    cudaGetSymbolAddress((void**)&pxt,   g_xt);
    cudaGetSymbolAddress((void**)&pdl,   g_delta);
    cudaGetSymbolAddress((void**)&pG,    g_G);
    cudaGetSymbolAddress((void**)&pm2t,  g_m2t);
    cudaGetSymbolAddress((void**)&pmu,   g_muT);
    cudaGetSymbolAddress((void**)&pab,   g_AB);
    cudaGetSymbolAddress((void**)&pP,    g_part);

    cudaFuncSetAttribute(tgemm<0>, cudaFuncAttributeMaxDynamicSharedMemorySize, SMEM_SZ);
    cudaFuncSetAttribute(tgemm<1>, cudaFuncAttributeMaxDynamicSharedMemorySize, SMEM_SZ);
    cudaFuncSetAttribute(tgemm<2>, cudaFuncAttributeMaxDynamicSharedMemorySize, SMEM_SZ);

    /* Side stream for the Phi-bank chain (depends only on m_y/m_u) + m_phi round. */
    cudaStream_t s1;
    cudaEvent_t evF, evP, evU, ev1;
    cudaStreamCreateWithFlags(&s1, cudaStreamNonBlocking);
    cudaEventCreateWithFlags(&evF, cudaEventDisableTiming);
    cudaEventCreateWithFlags(&evP, cudaEventDisableTiming);
    cudaEventCreateWithFlags(&evU, cudaEventDisableTiming);
    cudaEventCreateWithFlags(&ev1, cudaEventDisableTiming);

    /* fork: s1 joins the capture graph by waiting on an origin-stream event */
    cudaEventRecord(evF, 0);
    cudaStreamWaitEvent(s1, evF, 0);

    /* ---- stream 0: input-dependent chain ---- */
    prep_vp  <<<(L * KF + 255) / 256, 256>>>(evals, evecs);
    round_arr<<<(L * D + 255) / 256, 256>>>(u, puR, L * D);
    cudaEventRecord(evU, 0);

    /* conv: X_k = Toeplitz(vp_k) @ U (triangular), into x_tilde layout; round out */
    tgemm<2><<<dim3(D / 128, L / 128, KF), TPB, SMEM_SZ>>>(
        pvp, puR, pxt, L, 0, D, KD, 0, 1, 0, L, 0, D);

    /* ---- stream 1: weight-only chain, overlapped with conv ---- */
    round_arr<<<(KD * D + 255) / 256, 256, 0, s1>>>(m_phi, pphiR, KD * D);
    cudaEventRecord(evP, s1);
    prep_mats<<<(DD + 255) / 256, 256, 0, s1>>>(m_y, m_u);

    /* Phi^T bank by doubling: G_{m+i} = G_m G_i + (G_{m-1} M2^T) G_{i-1}
       = [RT | G_m] @ [G_{i-1}; G_i] (stacked B contiguous in bank).
       Last stage builds only up to G_26 (batch 10).                    */
    const int mv[5] = {1, 2, 4, 8, 16};
    const int bc[5] = {1, 2, 4, 8, 10};
    for (int s = 0; s < 5; s++) {
        int m = mv[s];
        tgemm<0><<<dim3(D / 128, D / 128), TPB, SMEM_SZ, s1>>>(
            pG + (size_t)(m - 1) * DD, pm2t, pab, D, D, D, 2 * D, 0, 1, 0, 0, 0, 0);
        copy_gm<<<(DD + 255) / 256, 256, 0, s1>>>(m);
        tgemm<0><<<dim3(D / 128, D / 128, bc[s]), TPB, SMEM_SZ, s1>>>(
            pab, pG, pG + (size_t)(m + 1) * DD, 2 * D, 2 * D, D, D, 0, 1, 0, 0, DD, DD);
    }
    /* delta_ar_u -> partial 3 (needs rounded u from stream 0) */
    cudaStreamWaitEvent(s1, evU, 0);
    tgemm<1><<<dim3(D / 128, L / 128), TPB, SMEM_SZ, s1>>>(
        puR, pmu, pP + (size_t)3 * L * D, 3 * D, D, D, D, 0, 0, 0, 0, 0, 0);
    cudaEventRecord(ev1, s1);

    /* ---- stream 0 continues: phi GEMM (needs rounded m_phi) ---- */
    cudaStreamWaitEvent(0, evP, 0);
    /* delta_phi = x_tilde @ m_phi, split-K x3 (K=6144 each, 288 CTAs = 1 wave) */
    tgemm<0><<<dim3(D / 128, L / 128, 3), TPB, SMEM_SZ>>>(
        pxt, pphiR, pP, KD / 3, KD, D, D, 0, 0, 0, KD / 3, (KD / 3) * D, L * D);

    /* join: AR partial + Phi bank ready */
    cudaStreamWaitEvent(0, ev1, 0);
    /* delta = sum of 4 partials, tf32-rounded */
    reduce_p<<<(L * D / 4 + 255) / 256, 256>>>(pP, 4, pdl, 1);

    /* y = sum_{j=0}^{26} shift_j(delta) @ G_j : multishift GEMM, 27 slabs split x3 */
    tgemm<1><<<dim3(D / 128, L / 128, 3), TPB, SMEM_SZ>>>(
        pdl, pG, pP, 9 * D, D, D, D, 0, 0, 9, 0, 9 * DD, L * D);
    reduce_p<<<(L * D / 4 + 255) / 256, 256>>>(pP, 3, y, 0);
}

// round 9
// speedup vs baseline: 5.0964x; 1.1079x over previous
#include <cuda_runtime.h>
#include <math.h>
#include <cstdint>

#define L    2048
#define D    768
#define KF   24
#define KD   (KF * D)        /* 18432 */
#define JT   26              /* FIR truncation of the y-recurrence (27 taps, 3x9 split) */
#define DD   (D * D)

#define NS   3               /* cp.async pipeline stages (BK=32 per stage) */
#define TPB  256

/* SMEM per stage (floats): A 128 rows x 36 (32 used, 144B stride) = 4608,
   B 32 rows x 136 (128 used) = 4352. Stage = 8960 floats = 35840 B.      */
#define B_STRIDE_F 136
#define STAGE_F    8960
#define SMEM_SZ    (NS * STAGE_F * 4)

/* ---------------- scratch (device globals; no allocation allowed) ---------------- */
__device__ float g_vpT[KF * L];            /* filters * eig^(1/4), [k][t], tf32    */
__device__ float g_uR[L * D];              /* tf32-rounded inputs                  */
__device__ float g_phiR[(size_t)KD * D];   /* tf32-rounded m_phi                   */
__device__ float g_xt[(size_t)L * KD];     /* x_tilde [l][k*D+d]                   */
__device__ float g_delta[L * D];           /* delta_phi + delta_ar_u               */
__device__ float g_G[(JT + 1) * DD];       /* G_j = Phi_j^T bank (contiguous)      */
__device__ float g_m2t[DD];                /* M2^T (tf32)                          */
__device__ float g_muT[3 * DD];            /* m_u per lag [k][i][o] (tf32)         */
__device__ float g_AB[D * 2 * D];          /* [RT | G_m] concat for doubling       */
__device__ float g_part[5 * L * D];        /* split-K partial outputs              */

/* ---------------- helpers ---------------- */
__device__ __forceinline__ uint32_t s2u(const void* p) {
    uint32_t a;
    asm("{ .reg .u64 t; cvta.to.shared.u64 t, %1; cvt.u32.u64 %0, t; }" : "=r"(a) : "l"(p));
    return a;
}
__device__ __forceinline__ float tf32r(float x) {      /* round-to-nearest tf32 */
    float r; asm("cvt.rna.tf32.f32 %0, %1;" : "=f"(r) : "f"(x)); return r;
}

/* ---------------- small prep kernels ---------------- */
__global__ void prep_vp(const float* __restrict__ evals, const float* __restrict__ evecs) {
    int idx = blockIdx.x * blockDim.x + threadIdx.x;
    if (idx >= L * KF) return;
    int t = idx / KF, k = idx - t * KF;
    g_vpT[k * L + t] = tf32r(evecs[idx] * powf(evals[k], 0.25f));
}

__global__ void round_arr(const float* __restrict__ s, float* __restrict__ d, int n) {
    int i = blockIdx.x * blockDim.x + threadIdx.x;
    if (i < n) d[i] = tf32r(s[i]);
}

__global__ void prep_mats(const float* __restrict__ m_y, const float* __restrict__ m_u) {
    int idx = blockIdx.x * blockDim.x + threadIdx.x;
    if (idx >= DD) return;
    int i = idx / D, o = idx - i * D;                    /* write [i][o] */
    g_m2t[idx] = tf32r(m_y[(o * 2 + 1) * D + i]);        /* M2^T */
#pragma unroll
    for (int k = 0; k < 3; k++)
        g_muT[k * DD + idx] = tf32r(m_u[((size_t)o * D + i) * 3 + k]);
    g_G[idx] = (i == o) ? 1.f : 0.f;                     /* G_0 = I    */
    g_G[DD + idx] = tf32r(m_y[(o * 2 + 0) * D + i]);     /* G_1 = M1^T */
}

__global__ void copy_gm(int m) {                         /* g_AB[:, 768:1536] = G_m */
    int idx = blockIdx.x * blockDim.x + threadIdx.x;
    if (idx >= DD) return;
    int r = idx / D, c = idx - r * D;
    g_AB[r * (2 * D) + D + c] = g_G[(size_t)m * DD + idx];
}

/* reduce np split-K partials (stride L*D) -> out; optional tf32 round. float4 wide. */
__global__ void reduce_p(const float* __restrict__ p, int np, float* __restrict__ out, int rnd) {
    int i = blockIdx.x * blockDim.x + threadIdx.x;
    if (i >= (L * D) / 4) return;
    float4 s = ((const float4*)p)[i];
    for (int z = 1; z < np; z++) {
        float4 v = ((const float4*)(p + (size_t)z * L * D))[i];
        s.x += v.x; s.y += v.y; s.z += v.z; s.w += v.w;
    }
    if (rnd) { s.x = tf32r(s.x); s.y = tf32r(s.y); s.z = tf32r(s.z); s.w = tf32r(s.w); }
    ((float4*)out)[i] = s;
}

/* ---------------- mma.sync tf32 GEMM: C[128x128 tile] (+)= op(A) @ B ----------------
   BK = 32 per pipeline stage (4 k-sub-steps of 8).
   MODE 0 NORMAL : A[row, k]   = A[(row0+r)*lda + k0+k]
   MODE 1 MSHIFT : per-K-slab row shift j = jzs*z + k0/D (BK=32 never straddles a slab)
   MODE 2 TOEP   : A[row, k]   = vp[row - k - 2] (0 if neg); triangular Kend;
                   y-blocks reversed so heaviest CTAs launch first (work-steal balance).
   Batched / split-K over blockIdx.z with element strides aB/bB/cB.                    */
template <int MODE>
__global__ void __launch_bounds__(TPB, 2)
tgemm(const float* __restrict__ A, const float* __restrict__ B, float* __restrict__ C,
      int K, int lda, int ldb, int ldc, int beta, int rnd, int jzs,
      int aB, int bB, int cB) {
    extern __shared__ float sm[];
    A += (size_t)blockIdx.z * aB;
    B += (size_t)blockIdx.z * bB;
    C += (size_t)blockIdx.z * cB;
    const int jbase = jzs * blockIdx.z;

    const int yb = (MODE == 2) ? (gridDim.y - 1 - blockIdx.y) : blockIdx.y;
    const int row0 = yb * 128, col0 = blockIdx.x * 128;
    const int tid = threadIdx.x, lane = tid & 31, wid = tid >> 5;
    const int wm = wid & 1, wn = wid >> 1;       /* warp tile: 64 rows x 32 cols */
    const int g = lane >> 2, tig = lane & 3;

    const int Kend = (MODE == 2) ? min(K, row0 + 128) : K;
    const int T = Kend >> 5;

    float c[4][4][4];
#pragma unroll
    for (int a = 0; a < 4; a++)
#pragma unroll
        for (int b = 0; b < 4; b++)
#pragma unroll
            for (int e = 0; e < 4; e++) c[a][b][e] = 0.f;

    auto load_stage = [&](int st, int k0) {
        float* As = sm + st * STAGE_F;
        float* Bs = As + 4608;
        uint32_t abase = s2u(As), bbase = s2u(Bs);
        /* A tile: 128 rows x 32 k = 1024 16B chunks (144B row stride) */
#pragma unroll
        for (int q = 0; q < 4; q++) {
            int id = tid + q * 256;
            int r = id >> 3, c8 = id & 7;
            uint32_t dst = abase + r * 144 + c8 * 16;
            if (MODE == 2) {
                int kk = k0 + c8 * 4;
                int t0 = row0 + r - 2 - kk;
                float4 v;
                v.x = (t0 >= 0) ? A[t0]     : 0.f;
                v.y = (t0 >= 1) ? A[t0 - 1] : 0.f;
                v.z = (t0 >= 2) ? A[t0 - 2] : 0.f;
                v.w = (t0 >= 3) ? A[t0 - 3] : 0.f;
                *(float4*)((char*)As + r * 144 + c8 * 16) = v;
            } else if (MODE == 1) {
                int j = jbase + k0 / D, colb = k0 - (k0 / D) * D;
                int gr = row0 + r - j;
                const float* src = A + (size_t)max(gr, 0) * lda + colb + c8 * 4;
                uint32_t sz = (gr >= 0) ? 16u : 0u;
                asm volatile("cp.async.cg.shared.global [%0], [%1], 16, %2;"
                             :: "r"(dst), "l"(src), "r"(sz) : "memory");
            } else {
                const float* src = A + (size_t)(row0 + r) * lda + k0 + c8 * 4;
                asm volatile("cp.async.cg.shared.global [%0], [%1], 16;"
                             :: "r"(dst), "l"(src) : "memory");
            }
        }
        /* B tile: 32 k-rows x 128 n = 1024 chunks */
#pragma unroll
        for (int q = 0; q < 4; q++) {
            int id = tid + q * 256;
            int kr = id >> 5, c4 = id & 31;
            uint32_t dst = bbase + kr * (B_STRIDE_F * 4) + c4 * 16;
            const float* src = B + (size_t)(k0 + kr) * ldb + col0 + c4 * 4;
            asm volatile("cp.async.cg.shared.global [%0], [%1], 16;"
                         :: "r"(dst), "l"(src) : "memory");
        }
    };

    /* prologue: stages 0..NS-2 */
#pragma unroll
    for (int s = 0; s < NS - 1; s++) {
        if (s < T) load_stage(s, s * 32);
        asm volatile("cp.async.commit_group;" ::: "memory");
    }

    for (int t = 0; t < T; t++) {
        asm volatile("cp.async.wait_group %0;" :: "n"(NS - 2) : "memory");
        __syncthreads();
        if (t + NS - 1 < T) load_stage((t + NS - 1) % NS, (t + NS - 1) * 32);
        asm volatile("cp.async.commit_group;" ::: "memory");

        float* As = sm + (t % NS) * STAGE_F;
        const uint32_t* Bsu = (const uint32_t*)(As + 4608);
        uint32_t abase = s2u(As);
#pragma unroll
        for (int kst = 0; kst < 4; kst++) {
            uint32_t af[4][4];
#pragma unroll
            for (int mt = 0; mt < 4; mt++) {
                uint32_t addr = abase + (wm * 64 + mt * 16 + (lane & 15)) * 144
                              + kst * 32 + ((lane >> 4) << 4);
                asm volatile("ldmatrix.sync.aligned.m8n8.x4.shared.b16 {%0,%1,%2,%3}, [%4];"
                    : "=r"(af[mt][0]), "=r"(af[mt][1]), "=r"(af[mt][2]), "=r"(af[mt][3])
                    : "r"(addr));
            }
            uint32_t bf[4][2];
#pragma unroll
            for (int nt = 0; nt < 4; nt++) {
                int nn = wn * 32 + nt * 8 + g;
                bf[nt][0] = Bsu[(kst * 8 + tig) * B_STRIDE_F + nn];
                bf[nt][1] = Bsu[(kst * 8 + tig + 4) * B_STRIDE_F + nn];
            }
#pragma unroll
            for (int mt = 0; mt < 4; mt++)
#pragma unroll
                for (int nt = 0; nt < 4; nt++)
                    asm volatile("mma.sync.aligned.m16n8k8.row.col.f32.tf32.tf32.f32 "
                        "{%0,%1,%2,%3},{%4,%5,%6,%7},{%8,%9},{%0,%1,%2,%3};"
                        : "+f"(c[mt][nt][0]), "+f"(c[mt][nt][1]),
                          "+f"(c[mt][nt][2]), "+f"(c[mt][nt][3])
                        : "r"(af[mt][0]), "r"(af[mt][1]), "r"(af[mt][2]), "r"(af[mt][3]),
                          "r"(bf[nt][0]), "r"(bf[nt][1]));
        }
    }

    /* epilogue */
#pragma unroll
    for (int mt = 0; mt < 4; mt++)
#pragma unroll
        for (int nt = 0; nt < 4; nt++) {
            int rr = row0 + wm * 64 + mt * 16 + g;
            int cc = col0 + wn * 32 + nt * 8 + tig * 2;
            float2* p0 = (float2*)&C[(size_t)rr * ldc + cc];
            float2* p1 = (float2*)&C[(size_t)(rr + 8) * ldc + cc];
            float2 v0 = make_float2(c[mt][nt][0], c[mt][nt][1]);
            float2 v1 = make_float2(c[mt][nt][2], c[mt][nt][3]);
            if (beta) {
                float2 o0 = *p0, o1 = *p1;
                v0.x += o0.x; v0.y += o0.y; v1.x += o1.x; v1.y += o1.y;
            }
            if (rnd) {
                v0.x = tf32r(v0.x); v0.y = tf32r(v0.y);
                v1.x = tf32r(v1.x); v1.y = tf32r(v1.y);
            }
            *p0 = v0; *p1 = v1;
        }
}

/* ---------------- launch ---------------- */
extern "C" void kernel_launch(void* const* d_in, const int* in_sizes, int n_in,
                              void* d_out, int out_size) {
    const float* u      = (const float*)d_in[0];   /* [2048, 768]   */
    const float* m_y    = (const float*)d_in[1];   /* [768, 2, 768] */
    const float* m_u    = (const float*)d_in[2];   /* [768, 768, 3] */
    const float* m_phi  = (const float*)d_in[3];   /* [18432, 768]  */
    const float* evals  = (const float*)d_in[4];   /* [24]          */
    const float* evecs  = (const float*)d_in[5];   /* [2048, 24]    */
    float* y = (float*)d_out;                      /* [2048, 768]   */

    float *pvp, *puR, *pphiR, *pxt, *pdl, *pG, *pm2t, *pmu, *pab, *pP;
    cudaGetSymbolAddress((void**)&pvp,   g_vpT);
    cudaGetSymbolAddress((void**)&puR,   g_uR);
    cudaGetSymbolAddress((void**)&pphiR, g_phiR);
    cudaGetSymbolAddress((void**)&pxt,   g_xt);
    cudaGetSymbolAddress((void**)&pdl,   g_delta);
    cudaGetSymbolAddress((void**)&pG,    g_G);
    cudaGetSymbolAddress((void**)&pm2t,  g_m2t);
    cudaGetSymbolAddress((void**)&pmu,   g_muT);
    cudaGetSymbolAddress((void**)&pab,   g_AB);
    cudaGetSymbolAddress((void**)&pP,    g_part);

    cudaFuncSetAttribute(tgemm<0>, cudaFuncAttributeMaxDynamicSharedMemorySize, SMEM_SZ);
    cudaFuncSetAttribute(tgemm<1>, cudaFuncAttributeMaxDynamicSharedMemorySize, SMEM_SZ);
    cudaFuncSetAttribute(tgemm<2>, cudaFuncAttributeMaxDynamicSharedMemorySize, SMEM_SZ);

    /* Side stream for the Phi-bank chain (depends only on m_y/m_u) + m_phi round. */
    cudaStream_t s1;
    cudaEvent_t evF, evP, evU, ev1;
    cudaStreamCreateWithFlags(&s1, cudaStreamNonBlocking);
    cudaEventCreateWithFlags(&evF, cudaEventDisableTiming);
    cudaEventCreateWithFlags(&evP, cudaEventDisableTiming);
    cudaEventCreateWithFlags(&evU, cudaEventDisableTiming);
    cudaEventCreateWithFlags(&ev1, cudaEventDisableTiming);

    /* fork: s1 joins the capture graph by waiting on an origin-stream event */
    cudaEventRecord(evF, 0);
    cudaStreamWaitEvent(s1, evF, 0);

    /* ---- stream 0: input-dependent chain ---- */
    prep_vp  <<<(L * KF + 255) / 256, 256>>>(evals, evecs);
    round_arr<<<(L * D + 255) / 256, 256>>>(u, puR, L * D);
    cudaEventRecord(evU, 0);

    /* conv: X_k = Toeplitz(vp_k) @ U (triangular), into x_tilde layout; round out */
    tgemm<2><<<dim3(D / 128, L / 128, KF), TPB, SMEM_SZ>>>(
        pvp, puR, pxt, L, 0, D, KD, 0, 1, 0, L, 0, D);

    /* ---- stream 1: weight-only chain, overlapped with conv ---- */
    round_arr<<<(KD * D + 255) / 256, 256, 0, s1>>>(m_phi, pphiR, KD * D);
    cudaEventRecord(evP, s1);
    prep_mats<<<(DD + 255) / 256, 256, 0, s1>>>(m_y, m_u);

    /* Phi^T bank by doubling: G_{m+i} = G_m G_i + (G_{m-1} M2^T) G_{i-1}
       = [RT | G_m] @ [G_{i-1}; G_i] (stacked B contiguous in bank).
       Last stage builds only up to G_26 (batch 10).                    */
    const int mv[5] = {1, 2, 4, 8, 16};
    const int bc[5] = {1, 2, 4, 8, 10};
    for (int s = 0; s < 5; s++) {
        int m = mv[s];
        tgemm<0><<<dim3(D / 128, D / 128), TPB, SMEM_SZ, s1>>>(
            pG + (size_t)(m - 1) * DD, pm2t, pab, D, D, D, 2 * D, 0, 1, 0, 0, 0, 0);
        copy_gm<<<(DD + 255) / 256, 256, 0, s1>>>(m);
        tgemm<0><<<dim3(D / 128, D / 128, bc[s]), TPB, SMEM_SZ, s1>>>(
            pab, pG, pG + (size_t)(m + 1) * DD, 2 * D, 2 * D, D, D, 0, 1, 0, 0, DD, DD);
    }
    /* delta_ar_u -> partial 3 (needs rounded u from stream 0) */
    cudaStreamWaitEvent(s1, evU, 0);
    tgemm<1><<<dim3(D / 128, L / 128), TPB, SMEM_SZ, s1>>>(
        puR, pmu, pP + (size_t)3 * L * D, 3 * D, D, D, D, 0, 0, 0, 0, 0, 0);
    cudaEventRecord(ev1, s1);

    /* ---- stream 0 continues: phi GEMM (needs rounded m_phi) ---- */
    cudaStreamWaitEvent(0, evP, 0);
    /* delta_phi = x_tilde @ m_phi, split-K x3 (K=6144 each, 288 CTAs = 1 wave) */
    tgemm<0><<<dim3(D / 128, L / 128, 3), TPB, SMEM_SZ>>>(
        pxt, pphiR, pP, KD / 3, KD, D, D, 0, 0, 0, KD / 3, (KD / 3) * D, L * D);

    /* join: AR partial + Phi bank ready */
    cudaStreamWaitEvent(0, ev1, 0);
    /* delta = sum of 4 partials, tf32-rounded */
    reduce_p<<<(L * D / 4 + 255) / 256, 256>>>(pP, 4, pdl, 1);

    /* y = sum_{j=0}^{26} shift_j(delta) @ G_j : multishift GEMM, 27 slabs split x3 */
    tgemm<1><<<dim3(D / 128, L / 128, 3), TPB, SMEM_SZ>>>(
        pdl, pG, pP, 9 * D, D, D, D, 0, 0, 9, 0, 9 * DD, L * D);
    reduce_p<<<(L * D / 4 + 255) / 256, 256>>>(pP, 3, y, 0);
}

// round 10
// speedup vs baseline: 5.2756x; 1.0352x over previous
#include <cuda_runtime.h>
#include <math.h>
#include <cstdint>

#define L    2048
#define D    768
#define KF   24
#define KD   (KF * D)        /* 18432 */
#define JT   26              /* FIR truncation (27 taps, 3x9 split-K) */
#define DD   (D * D)

#define NS   3               /* cp.async pipeline stages (BK=32) */
#define TPB  256

/* SMEM per stage (floats): A 128 rows x 36 (144B stride) + B 128 rows x 36 = 9216 */
#define STAGE_F 9216
#define SMEM_SZ (NS * STAGE_F * 4)     /* 110592 B, 2 CTA/SM */

/* ---------------- scratch (device globals; no allocation allowed) ---------------- */
__device__ float g_vpT[KF * L];            /* filters * eig^(1/4), [k][t], tf32    */
__device__ float g_uR[L * D];              /* tf32 u, row-major (AR A-operand)     */
__device__ float g_uT[D * L];              /* tf32 u^T (conv B-operand)            */
__device__ float g_phiT[(size_t)D * KD];   /* tf32 m_phi^T [768][18432]            */
__device__ float g_xt[(size_t)L * KD];     /* x_tilde [l][k*D+d]                   */
__device__ float g_delta[L * D];           /* delta_phi + delta_ar_u               */
__device__ float g_H[(JT + 1) * DD];       /* H_j = Phi_j bank (row-major)         */
__device__ float g_Gm[DD];                 /* scratch: G_{m-1} = H_{m-1}^T         */
__device__ float g_m2[DD];                 /* M2 row-major (tf32)                  */
__device__ float g_muTT[D * 3 * D];        /* [o][lag*768+i] = m_u[o][i][lag]      */
__device__ float g_AB[D * 2 * D];          /* [G_m | RT] rows (doubling Bt)        */
__device__ float g_part[5 * L * D];        /* split-K partial outputs              */

/* ---------------- helpers ---------------- */
__device__ __forceinline__ uint32_t s2u(const void* p) {
    uint32_t a;
    asm("{ .reg .u64 t; cvta.to.shared.u64 t, %1; cvt.u32.u64 %0, t; }" : "=r"(a) : "l"(p));
    return a;
}
__device__ __forceinline__ float tf32r(float x) {      /* round-to-nearest tf32 */
    float r; asm("cvt.rna.tf32.f32 %0, %1;" : "=f"(r) : "f"(x)); return r;
}

/* ---------------- small prep kernels ---------------- */
__global__ void prep_vp(const float* __restrict__ evals, const float* __restrict__ evecs) {
    int idx = blockIdx.x * blockDim.x + threadIdx.x;
    if (idx >= L * KF) return;
    int t = idx / KF, k = idx - t * KF;
    g_vpT[k * L + t] = tf32r(evecs[idx] * powf(evals[k], 0.25f));
}

__global__ void round_arr(const float* __restrict__ s, float* __restrict__ d, int n) {
    int i = blockIdx.x * blockDim.x + threadIdx.x;
    if (i < n) d[i] = tf32r(s[i]);
}

__global__ void prep_mats(const float* __restrict__ m_y, const float* __restrict__ m_u) {
    int idx = blockIdx.x * blockDim.x + threadIdx.x;
    if (idx >= DD) return;
    int o = idx / D, i = idx - o * D;
    g_m2[idx]     = tf32r(m_y[(o * 2 + 1) * D + i]);   /* M2 row-major */
    g_H[DD + idx] = tf32r(m_y[(o * 2 + 0) * D + i]);   /* H_1 = M1     */
    g_H[idx]      = (i == o) ? 1.f : 0.f;              /* H_0 = I      */
#pragma unroll
    for (int lag = 0; lag < 3; lag++)
        g_muTT[(size_t)o * (3 * D) + lag * D + i] =
            tf32r(m_u[((size_t)o * D + i) * 3 + lag]);
}

/* tiled transpose: dst[c][r] = src[r][c]; grid (cols/32, rows/32), block (32,8) */
__global__ void transp(const float* __restrict__ s, float* __restrict__ d,
                       int lds, int ldd, int rnd) {
    __shared__ float t[32][33];
    int bx = blockIdx.x * 32, by = blockIdx.y * 32;
    int tx = threadIdx.x, ty = threadIdx.y;
#pragma unroll
    for (int i = 0; i < 4; i++)
        t[ty + i * 8][tx] = s[(size_t)(by + ty + i * 8) * lds + bx + tx];
    __syncthreads();
#pragma unroll
    for (int i = 0; i < 4; i++) {
        float v = t[tx][ty + i * 8];
        if (rnd) v = tf32r(v);
        d[(size_t)(bx + ty + i * 8) * ldd + by + tx] = v;
    }
}

/* reduce np split-K partials (stride L*D) -> out; optional tf32 round */
__global__ void reduce_p(const float* __restrict__ p, int np, float* __restrict__ out, int rnd) {
    int i = blockIdx.x * blockDim.x + threadIdx.x;
    if (i >= (L * D) / 4) return;
    float4 s = ((const float4*)p)[i];
    for (int z = 1; z < np; z++) {
        float4 v = ((const float4*)(p + (size_t)z * L * D))[i];
        s.x += v.x; s.y += v.y; s.z += v.z; s.w += v.w;
    }
    if (rnd) { s.x = tf32r(s.x); s.y = tf32r(s.y); s.z = tf32r(s.z); s.w = tf32r(s.w); }
    ((float4*)out)[i] = s;
}

/* ---------------- mma.sync tf32 GEMM: C[128x128 tile] = op(A) @ B ----------------
   B is stored TRANSPOSED globally (Bt[n][k], ldbt) and n-major in SMEM; fragments
   via ldmatrix (b16-pair trick). Optional per-k-slab B offset jB*bjmul.
   MODE 0: A[row][k0+k] plain.
   MODE 1: per-K-slab A offset: j = jzs*z + k0/D; addr -= j*jmul; if causal,
           zero-fill when row0+r-j < 0 (jmul=lda: row shift; jmul=DD: matrix hop).
   MODE 2: Toeplitz A from vp (row - k - 2); triangular Kend; y-blocks reversed. */
template <int MODE>
__global__ void __launch_bounds__(TPB, 2)
tgemm(const float* __restrict__ A, const float* __restrict__ B, float* __restrict__ C,
      int K, int lda, int ldbt, int ldc, int rnd, int jzs, int jmul, int causal,
      int bjmul, int aB, int bB, int cB) {
    extern __shared__ float sm[];
    A += (size_t)blockIdx.z * aB;
    B += (size_t)blockIdx.z * bB;
    C += (size_t)blockIdx.z * cB;
    const int jbase = jzs * blockIdx.z;

    const int yb = (MODE == 2) ? (gridDim.y - 1 - blockIdx.y) : blockIdx.y;
    const int row0 = yb * 128, col0 = blockIdx.x * 128;
    const int tid = threadIdx.x, lane = tid & 31, wid = tid >> 5;
    const int wm = wid & 1, wn = wid >> 1;       /* warp tile: 64 rows x 32 cols */
    const int g = lane >> 2, tig = lane & 3;

    const int Kend = (MODE == 2) ? min(K, row0 + 128) : K;
    const int T = Kend >> 5;

    float c[4][4][4];
#pragma unroll
    for (int a = 0; a < 4; a++)
#pragma unroll
        for (int b = 0; b < 4; b++)
#pragma unroll
            for (int e = 0; e < 4; e++) c[a][b][e] = 0.f;

    auto load_stage = [&](int st, int k0) {
        float* As = sm + st * STAGE_F;
        uint32_t abase = s2u(As), bbase = abase + 4608 * 4;
        /* A tile: 128 rows x 32 k (144B row stride) */
#pragma unroll
        for (int q = 0; q < 4; q++) {
            int id = tid + q * 256;
            int r = id >> 3, c8 = id & 7;
            uint32_t dst = abase + r * 144 + c8 * 16;
            if (MODE == 2) {
                int kk = k0 + c8 * 4;
                int t0 = row0 + r - 2 - kk;
                float4 v;
                v.x = (t0 >= 0) ? A[t0]     : 0.f;
                v.y = (t0 >= 1) ? A[t0 - 1] : 0.f;
                v.z = (t0 >= 2) ? A[t0 - 2] : 0.f;
                v.w = (t0 >= 3) ? A[t0 - 3] : 0.f;
                *(float4*)((char*)As + r * 144 + c8 * 16) = v;
            } else if (MODE == 1) {
                int jq = k0 / D;
                int j = jbase + jq;
                int colb = k0 - jq * D;
                long off = (long)(row0 + r) * lda + colb + c8 * 4 - (long)j * jmul;
                uint32_t sz = (!causal || (row0 + r - j >= 0)) ? 16u : 0u;
                const float* src = A + (sz ? off : 0);
                asm volatile("cp.async.cg.shared.global [%0], [%1], 16, %2;"
                             :: "r"(dst), "l"(src), "r"(sz) : "memory");
            } else {
                const float* src = A + (size_t)(row0 + r) * lda + k0 + c8 * 4;
                asm volatile("cp.async.cg.shared.global [%0], [%1], 16;"
                             :: "r"(dst), "l"(src) : "memory");
            }
        }
        /* B tile (n-major): 128 n-rows x 32 k (144B row stride) */
        {
            int jB = k0 / D;
#pragma unroll
            for (int q = 0; q < 4; q++) {
                int id = tid + q * 256;
                int r = id >> 3, c8 = id & 7;
                uint32_t dst = bbase + r * 144 + c8 * 16;
                const float* src = B + (size_t)(col0 + r) * ldbt + k0 + c8 * 4
                                 + (size_t)jB * bjmul;
                asm volatile("cp.async.cg.shared.global [%0], [%1], 16;"
                             :: "r"(dst), "l"(src) : "memory");
            }
        }
    };

    /* prologue */
#pragma unroll
    for (int s = 0; s < NS - 1; s++) {
        if (s < T) load_stage(s, s * 32);
        asm volatile("cp.async.commit_group;" ::: "memory");
    }

    for (int t = 0; t < T; t++) {
        asm volatile("cp.async.wait_group %0;" :: "n"(NS - 2) : "memory");
        __syncthreads();
        if (t + NS - 1 < T) load_stage((t + NS - 1) % NS, (t + NS - 1) * 32);
        asm volatile("cp.async.commit_group;" ::: "memory");

        float* As = sm + (t % NS) * STAGE_F;
        uint32_t abase = s2u(As);
        uint32_t bbase = abase + 4608 * 4;
        /* B ldmatrix per-warp base: grp = lane>>3 selects (nt half, k chunk) */
        const int grp = lane >> 3, l8 = lane & 7;
        uint32_t bB0 = bbase + (wn * 32 + (grp >> 1) * 8 + l8) * 144 + (grp & 1) * 16;
#pragma unroll
        for (int kst = 0; kst < 4; kst++) {
            uint32_t af[4][4];
#pragma unroll
            for (int mt = 0; mt < 4; mt++) {
                uint32_t addr = abase + (wm * 64 + mt * 16 + (lane & 15)) * 144
                              + kst * 32 + ((lane >> 4) << 4);
                asm volatile("ldmatrix.sync.aligned.m8n8.x4.shared.b16 {%0,%1,%2,%3}, [%4];"
                    : "=r"(af[mt][0]), "=r"(af[mt][1]), "=r"(af[mt][2]), "=r"(af[mt][3])
                    : "r"(addr));
            }
            uint32_t bf[4][2];
            asm volatile("ldmatrix.sync.aligned.m8n8.x4.shared.b16 {%0,%1,%2,%3}, [%4];"
                : "=r"(bf[0][0]), "=r"(bf[0][1]), "=r"(bf[1][0]), "=r"(bf[1][1])
                : "r"(bB0 + kst * 32));
            asm volatile("ldmatrix.sync.aligned.m8n8.x4.shared.b16 {%0,%1,%2,%3}, [%4];"
                : "=r"(bf[2][0]), "=r"(bf[2][1]), "=r"(bf[3][0]), "=r"(bf[3][1])
                : "r"(bB0 + 2304 + kst * 32));
#pragma unroll
            for (int mt = 0; mt < 4; mt++)
#pragma unroll
                for (int nt = 0; nt < 4; nt++)
                    asm volatile("mma.sync.aligned.m16n8k8.row.col.f32.tf32.tf32.f32 "
                        "{%0,%1,%2,%3},{%4,%5,%6,%7},{%8,%9},{%0,%1,%2,%3};"
                        : "+f"(c[mt][nt][0]), "+f"(c[mt][nt][1]),
                          "+f"(c[mt][nt][2]), "+f"(c[mt][nt][3])
                        : "r"(af[mt][0]), "r"(af[mt][1]), "r"(af[mt][2]), "r"(af[mt][3]),
                          "r"(bf[nt][0]), "r"(bf[nt][1]));
        }
    }

    /* epilogue */
#pragma unroll
    for (int mt = 0; mt < 4; mt++)
#pragma unroll
        for (int nt = 0; nt < 4; nt++) {
            int rr = row0 + wm * 64 + mt * 16 + g;
            int cc = col0 + wn * 32 + nt * 8 + tig * 2;
            float2 v0 = make_float2(c[mt][nt][0], c[mt][nt][1]);
            float2 v1 = make_float2(c[mt][nt][2], c[mt][nt][3]);
            if (rnd) {
                v0.x = tf32r(v0.x); v0.y = tf32r(v0.y);
                v1.x = tf32r(v1.x); v1.y = tf32r(v1.y);
            }
            *(float2*)&C[(size_t)rr * ldc + cc] = v0;
            *(float2*)&C[(size_t)(rr + 8) * ldc + cc] = v1;
        }
}

/* ---------------- launch ---------------- */
extern "C" void kernel_launch(void* const* d_in, const int* in_sizes, int n_in,
                              void* d_out, int out_size) {
    const float* u      = (const float*)d_in[0];   /* [2048, 768]   */
    const float* m_y    = (const float*)d_in[1];   /* [768, 2, 768] */
    const float* m_u    = (const float*)d_in[2];   /* [768, 768, 3] */
    const float* m_phi  = (const float*)d_in[3];   /* [18432, 768]  */
    const float* evals  = (const float*)d_in[4];   /* [24]          */
    const float* evecs  = (const float*)d_in[5];   /* [2048, 24]    */
    float* y = (float*)d_out;                      /* [2048, 768]   */

    float *pvp, *puR, *puT, *pphiT, *pxt, *pdl, *pH, *pGm, *pm2, *pmuTT, *pab, *pP;
    cudaGetSymbolAddress((void**)&pvp,   g_vpT);
    cudaGetSymbolAddress((void**)&puR,   g_uR);
    cudaGetSymbolAddress((void**)&puT,   g_uT);
    cudaGetSymbolAddress((void**)&pphiT, g_phiT);
    cudaGetSymbolAddress((void**)&pxt,   g_xt);
    cudaGetSymbolAddress((void**)&pdl,   g_delta);
    cudaGetSymbolAddress((void**)&pH,    g_H);
    cudaGetSymbolAddress((void**)&pGm,   g_Gm);
    cudaGetSymbolAddress((void**)&pm2,   g_m2);
    cudaGetSymbolAddress((void**)&pmuTT, g_muTT);
    cudaGetSymbolAddress((void**)&pab,   g_AB);
    cudaGetSymbolAddress((void**)&pP,    g_part);

    cudaFuncSetAttribute(tgemm<0>, cudaFuncAttributeMaxDynamicSharedMemorySize, SMEM_SZ);
    cudaFuncSetAttribute(tgemm<1>, cudaFuncAttributeMaxDynamicSharedMemorySize, SMEM_SZ);
    cudaFuncSetAttribute(tgemm<2>, cudaFuncAttributeMaxDynamicSharedMemorySize, SMEM_SZ);

    cudaStream_t s1;
    cudaEvent_t evF, evP, evU, ev1;
    cudaStreamCreateWithFlags(&s1, cudaStreamNonBlocking);
    cudaEventCreateWithFlags(&evF, cudaEventDisableTiming);
    cudaEventCreateWithFlags(&evP, cudaEventDisableTiming);
    cudaEventCreateWithFlags(&evU, cudaEventDisableTiming);
    cudaEventCreateWithFlags(&ev1, cudaEventDisableTiming);

    cudaEventRecord(evF, 0);
    cudaStreamWaitEvent(s1, evF, 0);

    /* ---- stream 0: input-dependent chain ---- */
    prep_vp  <<<(L * KF + 255) / 256, 256>>>(evals, evecs);
    round_arr<<<(L * D + 255) / 256, 256>>>(u, puR, L * D);
    transp<<<dim3(D / 32, L / 32), dim3(32, 8)>>>(u, puT, D, L, 1);   /* uT, rounded */
    cudaEventRecord(evU, 0);

    /* conv: X_k = Toeplitz(vp_k) @ U (triangular); B = u^T */
    tgemm<2><<<dim3(D / 128, L / 128, KF), TPB, SMEM_SZ>>>(
        pvp, puT, pxt, L, 0, L, KD, 1, 0, 0, 0, 0, L, 0, D);

    /* ---- stream 1: weight-only chain ---- */
    transp<<<dim3(D / 32, KD / 32), dim3(32, 8), 0, s1>>>(m_phi, pphiT, D, KD, 1);
    cudaEventRecord(evP, s1);
    prep_mats<<<(DD + 255) / 256, 256, 0, s1>>>(m_y, m_u);

    /* Phi bank doubling: H_{m+i} = [H_i|H_{i-1}] @ [H_m ; M2 H_{m-1}],
       transposed fixed-B = [G_m | RT], RT = G_{m-1} @ M2^T (Bt = M2). */
    const int mv[5] = {1, 2, 4, 8, 16};
    const int bc[5] = {1, 2, 4, 8, 10};
    for (int s = 0; s < 5; s++) {
        int m = mv[s];
        transp<<<dim3(D / 32, D / 32), dim3(32, 8), 0, s1>>>(
            pH + (size_t)(m - 1) * DD, pGm, D, D, 0);           /* G_{m-1} */
        transp<<<dim3(D / 32, D / 32), dim3(32, 8), 0, s1>>>(
            pH + (size_t)m * DD, pab, D, 2 * D, 0);             /* G_m -> AB left */
        tgemm<0><<<dim3(D / 128, D / 128), TPB, SMEM_SZ, s1>>>( /* RT -> AB right */
            pGm, pm2, pab + D, D, D, D, 2 * D, 1, 0, 0, 0, 0, 0, 0, 0);
        tgemm<1><<<dim3(D / 128, D / 128, bc[s]), TPB, SMEM_SZ, s1>>>(
            pH + DD, pab, pH + (size_t)(m + 1) * DD, 2 * D, D, 2 * D, D,
            1, 0, DD, 0, 0, DD, 0, DD);
    }
    /* delta_ar_u -> partial 3 (A = uR causal-multishift, Bt = muTT) */
    cudaStreamWaitEvent(s1, evU, 0);
    tgemm<1><<<dim3(D / 128, L / 128), TPB, SMEM_SZ, s1>>>(
        puR, pmuTT, pP + (size_t)3 * L * D, 3 * D, D, 3 * D, D,
        0, 0, D, 1, 0, 0, 0, 0);
    cudaEventRecord(ev1, s1);

    /* ---- stream 0: phi GEMM (Bt = m_phi^T), split-K x3 ---- */
    cudaStreamWaitEvent(0, evP, 0);
    tgemm<0><<<dim3(D / 128, L / 128, 3), TPB, SMEM_SZ>>>(
        pxt, pphiT, pP, KD / 3, KD, KD, D, 0, 0, 0, 0, 0, KD / 3, KD / 3, L * D);

    cudaStreamWaitEvent(0, ev1, 0);
    reduce_p<<<(L * D / 4 + 255) / 256, 256>>>(pP, 4, pdl, 1);

    /* y = sum_{j=0}^{26} shift_j(delta) @ Phi_j^T : Bt = H bank, 3x9 split */
    tgemm<1><<<dim3(D / 128, L / 128, 3), TPB, SMEM_SZ>>>(
        pdl, pH, pP, 9 * D, D, D, D, 0, 9, D, 1, DD - D, 0, 9 * DD, L * D);
    reduce_p<<<(L * D / 4 + 255) / 256, 256>>>(pP, 3, y, 0);
}